// round 11
// baseline (speedup 1.0000x reference)
#include <cuda_runtime.h>
#include <cuda_fp16.h>
#include <cstdint>
#include <cstddef>

#define B_   128
#define S_   400
#define H_   512
#define E_   128
#define V_   50000
#define VEXT 50050
#define TWOH 1024

// ---------------- scratch (float offsets) ----------------
#define OFF_EPC    0u          // 128*1152
#define OFF_X      147456u     // 128*128
#define OFF_GATES  163840u     // 128*2048
#define OFF_SH     425984u     // 128*1024  (s_hat = [h,c])
#define OFF_WSH    557056u     // 128*1024  (s_hat@Ws.T + bs)
#define OFF_E      688128u     // 128*400
#define OFF_HC     739328u     // 128*1536  ([h, context])
#define OFF_HID    935936u     // 128*512
#define OFF_VSUM   1001472u    // 128
#define SCRATCH_TOTAL 1001600u

__device__ float g_scratch[SCRATCH_TOTAL];

// fp16 staging: enc + Wh + Wv2 + hid
#define HOFF_ENC 0u            // 52428800
#define HOFF_WH  52428800u     // 1048576
#define HOFF_WV2 53477376u     // 25600000
#define HOFF_HID 79077376u     // 65536
#define HALF_TOTAL 79142912u
__device__ __align__(16) __half g_half[HALF_TOTAL];

// ---------------- aux stream/events for fork-join graph capture ----------------
namespace {
struct Aux {
    cudaStream_t s = nullptr;
    cudaEvent_t e0 = nullptr, e1 = nullptr, e2 = nullptr;
    bool ok = false;
    Aux() {
        ok = (cudaStreamCreateWithFlags(&s, cudaStreamNonBlocking) == cudaSuccess) &&
             (cudaEventCreateWithFlags(&e0, cudaEventDisableTiming) == cudaSuccess) &&
             (cudaEventCreateWithFlags(&e1, cudaEventDisableTiming) == cudaSuccess) &&
             (cudaEventCreateWithFlags(&e2, cudaEventDisableTiming) == cudaSuccess);
    }
};
Aux g_aux;
}

// ---------------- helpers ----------------
__device__ __forceinline__ float f2tf32(float x) {
    uint32_t u;
    asm("cvt.rna.tf32.f32 %0, %1;" : "=r"(u) : "f"(x));
    return __uint_as_float(u);
}
__device__ __forceinline__ float fsig(float x) { return 1.0f / (1.0f + __expf(-x)); }
__device__ __forceinline__ float ftanh(float x) { return 1.0f - 2.0f / (1.0f + __expf(2.0f * x)); }

__device__ __forceinline__ uint32_t s2u(const void* p) {
    uint32_t a;
    asm("{ .reg .u64 t; cvta.to.shared.u64 t, %1; cvt.u32.u64 %0, t; }" : "=r"(a) : "l"(p));
    return a;
}

__device__ __forceinline__ void mma_tf32(float* c, const uint32_t* a, uint32_t b0, uint32_t b1) {
    asm volatile(
        "mma.sync.aligned.m16n8k8.row.col.f32.tf32.tf32.f32 "
        "{%0,%1,%2,%3},{%4,%5,%6,%7},{%8,%9},{%0,%1,%2,%3};\n"
        : "+f"(c[0]), "+f"(c[1]), "+f"(c[2]), "+f"(c[3])
        : "r"(a[0]), "r"(a[1]), "r"(a[2]), "r"(a[3]), "r"(b0), "r"(b1));
}

__device__ __forceinline__ void mma_f16(float* c, const uint32_t* a, uint32_t b0, uint32_t b1) {
    asm volatile(
        "mma.sync.aligned.m16n8k16.row.col.f32.f16.f16.f32 "
        "{%0,%1,%2,%3},{%4,%5,%6,%7},{%8,%9},{%0,%1,%2,%3};\n"
        : "+f"(c[0]), "+f"(c[1]), "+f"(c[2]), "+f"(c[3])
        : "r"(a[0]), "r"(a[1]), "r"(a[2]), "r"(a[3]), "r"(b0), "r"(b1));
}

#define LDSM4(r0, r1, r2, r3, addr) \
    asm volatile("ldmatrix.sync.aligned.m8n8.x4.shared.b16 {%0,%1,%2,%3}, [%4];" \
                 : "=r"(r0), "=r"(r1), "=r"(r2), "=r"(r3) : "r"(addr))

__device__ __forceinline__ void cp16(uint32_t dst, const void* src) {
    asm volatile("cp.async.cg.shared.global [%0], [%1], 16;" :: "r"(dst), "l"(src));
}
__device__ __forceinline__ void cp16z(uint32_t dst, const void* src, int sz) {
    asm volatile("cp.async.cg.shared.global [%0], [%1], 16, %2;" :: "r"(dst), "l"(src), "r"(sz));
}

// ---------------- fp32 -> fp16 staging ----------------
__global__ void k_convA(const float* __restrict__ enc, const float* __restrict__ Wh,
                        __half* __restrict__ hh) {
    int i = blockIdx.x * blockDim.x + threadIdx.x;
    if (i < 26214400) {
        float2 v = ((const float2*)enc)[i];
        ((__half2*)(hh + HOFF_ENC))[i] = __floats2half2_rn(v.x, v.y);
    } else if (i < 26738688) {
        int j = i - 26214400;
        float2 v = ((const float2*)Wh)[j];
        ((__half2*)(hh + HOFF_WH))[j] = __floats2half2_rn(v.x, v.y);
    }
}

__global__ void k_convB(const float* __restrict__ Wv2, __half* __restrict__ hh) {
    int i = blockIdx.x * blockDim.x + threadIdx.x;
    if (i < 12800000) {
        float2 v = ((const float2*)Wv2)[i];
        ((__half2*)(hh + HOFF_WV2))[i] = __floats2half2_rn(v.x, v.y);
    }
}

// hid fp32 -> fp16
__global__ void k_h2(const float* __restrict__ hid, __half* __restrict__ hidh) {
    int i = blockIdx.x * blockDim.x + threadIdx.x;
    if (i < 32768) {
        float2 v = ((const float2*)hid)[i];
        ((__half2*)hidh)[i] = __floats2half2_rn(v.x, v.y);
    }
}

// ---------------- fused prep: epc build + bias inits + e zero + vsum/fd-oov zero ----------------
__global__ void k_prep(const int* __restrict__ pt, const float* __restrict__ emb,
                       const float* __restrict__ pcv, const float* __restrict__ bxc,
                       const float* __restrict__ bs, const float* __restrict__ bv1,
                       float* __restrict__ epc, float* __restrict__ xbuf,
                       float* __restrict__ gbuf, float* __restrict__ wsh,
                       float* __restrict__ hid, float* __restrict__ ebuf,
                       float* __restrict__ vsum, float* __restrict__ fd) {
    int i = blockIdx.x * blockDim.x + threadIdx.x;
    if (i < 147456) {
        int b = i / 1152, c = i - b * 1152;
        epc[i] = (c < E_) ? emb[(size_t)pt[b] * E_ + c] : pcv[b * TWOH + (c - E_)];
        return;
    }
    i -= 147456;
    if (i < 16384) { xbuf[i] = bxc[i & 127]; return; }
    i -= 16384;
    if (i < 262144) { gbuf[i] = 0.f; return; }
    i -= 262144;
    if (i < 131072) { wsh[i] = bs[i & 1023]; return; }
    i -= 131072;
    if (i < 65536) { hid[i] = bv1[i & 511]; return; }
    i -= 65536;
    if (i < 51200) { ebuf[i] = 0.f; return; }
    i -= 51200;
    if (i < 128) { vsum[i] = 0.f; return; }
    i -= 128;
    if (i < 6400) {
        int b = i / 50, c = i - b * 50;
        fd[(size_t)b * VEXT + V_ + c] = 0.f;
    }
}

// ---------------- LSTM pointwise ----------------
__global__ void k_lstm(const float* __restrict__ gates, const float* __restrict__ c0,
                       const float* __restrict__ b_ih, const float* __restrict__ b_hh,
                       float* __restrict__ out_h, float* __restrict__ out_c,
                       float* __restrict__ sh, float* __restrict__ hc) {
    int idx = blockIdx.x * blockDim.x + threadIdx.x;
    if (idx >= B_ * H_) return;
    int b = idx >> 9, j = idx & 511;
    const float* gb = gates + b * 2048;
    float gi = gb[j]        + b_ih[j]        + b_hh[j];
    float gf = gb[512 + j]  + b_ih[512 + j]  + b_hh[512 + j];
    float gg = gb[1024 + j] + b_ih[1024 + j] + b_hh[1024 + j];
    float go = gb[1536 + j] + b_ih[1536 + j] + b_hh[1536 + j];
    float c = fsig(gf) * c0[idx] + fsig(gi) * tanhf(gg);
    float h = fsig(go) * tanhf(c);
    out_h[idx] = h;
    out_c[idx] = c;
    sh[b * TWOH + j] = h;
    sh[b * TWOH + H_ + j] = c;
    hc[b * 1536 + j] = h;
}

// ---------------- attention GEMM (round-6 proven config, UNCHANGED) ----------------
#define GA_BUF 30720

__global__ void __launch_bounds__(512)
gemma(const __half* __restrict__ Ah, const __half* __restrict__ Bh,
      const float* __restrict__ bh, const float* __restrict__ bcv,
      const float* __restrict__ sWs, const float* __restrict__ Wc,
      const float* __restrict__ vv, const float* __restrict__ cov,
      float* __restrict__ eout)
{
    extern __shared__ char sm[];
    uint32_t sbase = s2u(sm);
    int tid = threadIdx.x, lane = tid & 31, warp = tid >> 5;
    int wm = (warp & 1) * 64;
    int wn = (warp >> 1) * 32;
    int bm = blockIdx.y * 128, bn = blockIdx.x * 256;

    float acc[4][4][4];
#pragma unroll
    for (int i = 0; i < 4; i++)
#pragma unroll
        for (int j = 0; j < 4; j++)
#pragma unroll
            for (int l = 0; l < 4; l++) acc[i][j][l] = 0.f;

    int r = tid >> 2, c = tid & 3;
    const __half* Asrc  = Ah + (size_t)(bm + r) * 1024 + c * 8;
    const __half* Bsrc0 = Bh + (size_t)(bn + r) * 1024 + c * 8;
    const __half* Bsrc1 = Bh + (size_t)(bn + 128 + r) * 1024 + c * 8;
    uint32_t dA  = sbase + r * 80 + c * 16;
    uint32_t dB0 = sbase + 10240 + r * 80 + c * 16;
    uint32_t dB1 = sbase + 10240 + (128 + r) * 80 + c * 16;

    cp16(dA, Asrc); cp16(dB0, Bsrc0); cp16(dB1, Bsrc1);
    asm volatile("cp.async.commit_group;" ::: "memory");

    for (int kb = 0; kb < 32; kb++) {
        if (kb + 1 < 32) {
            int off = ((kb + 1) & 1) * GA_BUF;
            int kof = (kb + 1) * 32;
            cp16(dA + off, Asrc + kof);
            cp16(dB0 + off, Bsrc0 + kof);
            cp16(dB1 + off, Bsrc1 + kof);
            asm volatile("cp.async.commit_group;" ::: "memory");
            asm volatile("cp.async.wait_group 1;" ::: "memory");
        } else {
            asm volatile("cp.async.wait_group 0;" ::: "memory");
        }
        __syncthreads();

        uint32_t bo = (kb & 1) * GA_BUF;
        uint32_t arow = sbase + bo + (wm + (lane & 15)) * 80 + ((lane >> 4) << 4);
        uint32_t brow = sbase + bo + 10240 + (wn + (lane & 15)) * 80 + ((lane >> 4) << 4);
#pragma unroll
        for (int st = 0; st < 2; st++) {
            uint32_t kbyt = st * 32;
            uint32_t af[4][4], bf[4][2];
#pragma unroll
            for (int mi = 0; mi < 4; mi++)
                LDSM4(af[mi][0], af[mi][1], af[mi][2], af[mi][3],
                      arow + mi * (16 * 80) + kbyt);
#pragma unroll
            for (int nj = 0; nj < 2; nj++) {
                uint32_t q0, q1, q2, q3;
                LDSM4(q0, q1, q2, q3, brow + nj * (16 * 80) + kbyt);
                bf[nj * 2][0] = q0; bf[nj * 2 + 1][0] = q1;
                bf[nj * 2][1] = q2; bf[nj * 2 + 1][1] = q3;
            }
#pragma unroll
            for (int mi = 0; mi < 4; mi++)
#pragma unroll
                for (int ni = 0; ni < 4; ni++)
                    mma_f16(acc[mi][ni], af[mi], bf[ni][0], bf[ni][1]);
        }
        __syncthreads();
    }

    // fused attention epilogue
#pragma unroll
    for (int mi = 0; mi < 4; mi++) {
        int rr0 = bm + wm + mi * 16 + (lane >> 2);
        int rr1 = rr0 + 8;
        int b0 = rr0 / S_, b1 = rr1 / S_;
        float cv0 = cov[rr0], cv1 = cov[rr1];
        float p0 = 0.f, p1 = 0.f;
#pragma unroll
        for (int ni = 0; ni < 4; ni++) {
#pragma unroll
            for (int j = 0; j < 2; j++) {
                int n = bn + wn + ni * 8 + (lane & 3) * 2 + j;
                float base = bh[n] + bcv[n];
                float wc = Wc[n], vn = vv[n];
                p0 += ftanh(acc[mi][ni][j]     + base + sWs[b0 * TWOH + n] + cv0 * wc) * vn;
                p1 += ftanh(acc[mi][ni][2 + j] + base + sWs[b1 * TWOH + n] + cv1 * wc) * vn;
            }
        }
        p0 += __shfl_xor_sync(0xffffffffu, p0, 1);
        p0 += __shfl_xor_sync(0xffffffffu, p0, 2);
        p1 += __shfl_xor_sync(0xffffffffu, p1, 1);
        p1 += __shfl_xor_sync(0xffffffffu, p1, 2);
        if ((lane & 3) == 0) {
            atomicAdd(&eout[rr0], p0);
            atomicAdd(&eout[rr1], p1);
        }
    }
}

// ---------------- logits GEMM: all-fp16, fused exp + rowsum epilogue ----------------
__global__ void __launch_bounds__(512)
gemml(const __half* __restrict__ Ah, const __half* __restrict__ Bh,
      const float* __restrict__ bias, float* __restrict__ fd,
      float* __restrict__ vsum, int N)
{
    extern __shared__ char sm[];
    uint32_t sbase = s2u(sm);
    int tid = threadIdx.x, lane = tid & 31, warp = tid >> 5;
    int wm = (warp & 1) * 64;
    int wn = (warp >> 1) * 32;
    int bm = blockIdx.y * 128, bn = blockIdx.x * 256;

    float acc[4][4][4];
#pragma unroll
    for (int i = 0; i < 4; i++)
#pragma unroll
        for (int j = 0; j < 4; j++)
#pragma unroll
            for (int l = 0; l < 4; l++) acc[i][j][l] = 0.f;

    int r = tid >> 2, c = tid & 3;
    int n0 = bn + r, n1 = bn + 128 + r;
    int s0 = (n0 < N) ? 16 : 0, s1 = (n1 < N) ? 16 : 0;
    const __half* Asrc  = Ah + (size_t)(bm + r) * 512 + c * 8;
    const __half* Bsrc0 = Bh + (size_t)n0 * 512 + c * 8;
    const __half* Bsrc1 = Bh + (size_t)n1 * 512 + c * 8;
    uint32_t dA  = sbase + r * 80 + c * 16;
    uint32_t dB0 = sbase + 10240 + r * 80 + c * 16;
    uint32_t dB1 = sbase + 10240 + (128 + r) * 80 + c * 16;

    cp16(dA, Asrc); cp16z(dB0, Bsrc0, s0); cp16z(dB1, Bsrc1, s1);
    asm volatile("cp.async.commit_group;" ::: "memory");

    for (int kb = 0; kb < 16; kb++) {
        if (kb + 1 < 16) {
            int off = ((kb + 1) & 1) * GA_BUF;
            int kof = (kb + 1) * 32;
            cp16(dA + off, Asrc + kof);
            cp16z(dB0 + off, Bsrc0 + kof, s0);
            cp16z(dB1 + off, Bsrc1 + kof, s1);
            asm volatile("cp.async.commit_group;" ::: "memory");
            asm volatile("cp.async.wait_group 1;" ::: "memory");
        } else {
            asm volatile("cp.async.wait_group 0;" ::: "memory");
        }
        __syncthreads();

        uint32_t bo = (kb & 1) * GA_BUF;
        uint32_t arow = sbase + bo + (wm + (lane & 15)) * 80 + ((lane >> 4) << 4);
        uint32_t brow = sbase + bo + 10240 + (wn + (lane & 15)) * 80 + ((lane >> 4) << 4);
#pragma unroll
        for (int st = 0; st < 2; st++) {
            uint32_t kbyt = st * 32;
            uint32_t af[4][4], bf[4][2];
#pragma unroll
            for (int mi = 0; mi < 4; mi++)
                LDSM4(af[mi][0], af[mi][1], af[mi][2], af[mi][3],
                      arow + mi * (16 * 80) + kbyt);
#pragma unroll
            for (int nj = 0; nj < 2; nj++) {
                uint32_t q0, q1, q2, q3;
                LDSM4(q0, q1, q2, q3, brow + nj * (16 * 80) + kbyt);
                bf[nj * 2][0] = q0; bf[nj * 2 + 1][0] = q1;
                bf[nj * 2][1] = q2; bf[nj * 2 + 1][1] = q3;
            }
#pragma unroll
            for (int mi = 0; mi < 4; mi++)
#pragma unroll
                for (int ni = 0; ni < 4; ni++)
                    mma_f16(acc[mi][ni], af[mi], bf[ni][0], bf[ni][1]);
        }
        __syncthreads();
    }

    // epilogue: exp(logit) -> fd, quad-reduced row sums -> vsum
#pragma unroll
    for (int mi = 0; mi < 4; mi++) {
        int rr = bm + wm + mi * 16 + (lane >> 2);
        float s0r = 0.f, s1r = 0.f;
#pragma unroll
        for (int ni = 0; ni < 4; ni++) {
            int cn = bn + wn + ni * 8 + (lane & 3) * 2;
#pragma unroll
            for (int j = 0; j < 2; j++) {
                if (cn + j < N) {
                    float bi = bias[cn + j];
                    float e0 = __expf(acc[mi][ni][j] + bi);
                    float e1 = __expf(acc[mi][ni][2 + j] + bi);
                    fd[(size_t)rr * VEXT + cn + j] = e0;
                    fd[(size_t)(rr + 8) * VEXT + cn + j] = e1;
                    s0r += e0;
                    s1r += e1;
                }
            }
        }
        s0r += __shfl_xor_sync(0xffffffffu, s0r, 1);
        s0r += __shfl_xor_sync(0xffffffffu, s0r, 2);
        s1r += __shfl_xor_sync(0xffffffffu, s1r, 1);
        s1r += __shfl_xor_sync(0xffffffffu, s1r, 2);
        if ((lane & 3) == 0) {
            atomicAdd(&vsum[rr], s0r);
            atomicAdd(&vsum[rr + 8], s1r);
        }
    }
}

// ---------------- small tf32 GEMM (mma.sync), split-K accumulate ----------------
#define BM 128
#define BN 128
#define BK 16

__global__ void __launch_bounds__(256)
gemm2(const float* __restrict__ A, const float* __restrict__ W,
      float* __restrict__ C, int M, int N, int K, int Kc)
{
    __shared__ float As[2][BK][BM + 4];
    __shared__ float Bs[2][BK][BN + 4];
    int tid = threadIdx.x;
    int lane = tid & 31, warp = tid >> 5;
    int wm = (warp & 1) * 64;
    int wn = (warp >> 1) * 32;
    int bm = blockIdx.y * BM, bn = blockIdx.x * BN;
    int k0 = blockIdx.z * Kc;
    int kend = k0 + Kc; if (kend > K) kend = K;

    float acc[4][4][4];
#pragma unroll
    for (int i = 0; i < 4; i++)
#pragma unroll
        for (int j = 0; j < 4; j++)
#pragma unroll
            for (int l = 0; l < 4; l++) acc[i][j][l] = 0.f;

    int ar = tid >> 2;
    int ac = (tid & 3) * 4;
    const float* Ap0 = A + (size_t)(bm + ar) * K + k0 + ac;
    const float* Ap1 = Ap0 + (size_t)64 * K;
    int nr0 = bn + ar, nr1 = nr0 + 64;
    const float* Wp0 = W + (size_t)nr0 * K + k0 + ac;
    const float* Wp1 = W + (size_t)nr1 * K + k0 + ac;
    bool vb0 = nr0 < N, vb1 = nr1 < N;

    float4 ra0 = *(const float4*)Ap0;
    float4 ra1 = *(const float4*)Ap1;
    float4 rb0 = vb0 ? *(const float4*)Wp0 : make_float4(0, 0, 0, 0);
    float4 rb1 = vb1 ? *(const float4*)Wp1 : make_float4(0, 0, 0, 0);

    int buf = 0;
    {
        As[0][ac + 0][ar] = f2tf32(ra0.x); As[0][ac + 1][ar] = f2tf32(ra0.y);
        As[0][ac + 2][ar] = f2tf32(ra0.z); As[0][ac + 3][ar] = f2tf32(ra0.w);
        As[0][ac + 0][ar + 64] = f2tf32(ra1.x); As[0][ac + 1][ar + 64] = f2tf32(ra1.y);
        As[0][ac + 2][ar + 64] = f2tf32(ra1.z); As[0][ac + 3][ar + 64] = f2tf32(ra1.w);
        Bs[0][ac + 0][ar] = f2tf32(rb0.x); Bs[0][ac + 1][ar] = f2tf32(rb0.y);
        Bs[0][ac + 2][ar] = f2tf32(rb0.z); Bs[0][ac + 3][ar] = f2tf32(rb0.w);
        Bs[0][ac + 0][ar + 64] = f2tf32(rb1.x); Bs[0][ac + 1][ar + 64] = f2tf32(rb1.y);
        Bs[0][ac + 2][ar + 64] = f2tf32(rb1.z); Bs[0][ac + 3][ar + 64] = f2tf32(rb1.w);
    }
    __syncthreads();

    for (int kk = k0; kk < kend; kk += BK) {
        bool more = (kk + BK) < kend;
        if (more) {
            int d = kk + BK - k0;
            ra0 = *(const float4*)(Ap0 + d);
            ra1 = *(const float4*)(Ap1 + d);
            rb0 = vb0 ? *(const float4*)(Wp0 + d) : make_float4(0, 0, 0, 0);
            rb1 = vb1 ? *(const float4*)(Wp1 + d) : make_float4(0, 0, 0, 0);
        }

#pragma unroll
        for (int ks = 0; ks < BK; ks += 8) {
            uint32_t af[4][4], bf[4][2];
            int kr = ks + (lane & 3);
#pragma unroll
            for (int mi = 0; mi < 4; mi++) {
                int m0 = wm + mi * 16 + (lane >> 2);
                af[mi][0] = __float_as_uint(As[buf][kr][m0]);
                af[mi][1] = __float_as_uint(As[buf][kr][m0 + 8]);
                af[mi][2] = __float_as_uint(As[buf][kr + 4][m0]);
                af[mi][3] = __float_as_uint(As[buf][kr + 4][m0 + 8]);
            }
#pragma unroll
            for (int ni = 0; ni < 4; ni++) {
                int n0 = wn + ni * 8 + (lane >> 2);
                bf[ni][0] = __float_as_uint(Bs[buf][kr][n0]);
                bf[ni][1] = __float_as_uint(Bs[buf][kr + 4][n0]);
            }
#pragma unroll
            for (int mi = 0; mi < 4; mi++)
#pragma unroll
                for (int ni = 0; ni < 4; ni++)
                    mma_tf32(acc[mi][ni], af[mi], bf[ni][0], bf[ni][1]);
        }

        if (more) {
            int nb = buf ^ 1;
            As[nb][ac + 0][ar] = f2tf32(ra0.x); As[nb][ac + 1][ar] = f2tf32(ra0.y);
            As[nb][ac + 2][ar] = f2tf32(ra0.z); As[nb][ac + 3][ar] = f2tf32(ra0.w);
            As[nb][ac + 0][ar + 64] = f2tf32(ra1.x); As[nb][ac + 1][ar + 64] = f2tf32(ra1.y);
            As[nb][ac + 2][ar + 64] = f2tf32(ra1.z); As[nb][ac + 3][ar + 64] = f2tf32(ra1.w);
            Bs[nb][ac + 0][ar] = f2tf32(rb0.x); Bs[nb][ac + 1][ar] = f2tf32(rb0.y);
            Bs[nb][ac + 2][ar] = f2tf32(rb0.z); Bs[nb][ac + 3][ar] = f2tf32(rb0.w);
            Bs[nb][ac + 0][ar + 64] = f2tf32(rb1.x); Bs[nb][ac + 1][ar + 64] = f2tf32(rb1.y);
            Bs[nb][ac + 2][ar + 64] = f2tf32(rb1.z); Bs[nb][ac + 3][ar + 64] = f2tf32(rb1.w);
            __syncthreads();
            buf = nb;
        }
    }

#pragma unroll
    for (int mi = 0; mi < 4; mi++) {
        int r = bm + wm + mi * 16 + (lane >> 2);
#pragma unroll
        for (int ni = 0; ni < 4; ni++) {
            int cn = bn + wn + ni * 8 + (lane & 3) * 2;
            if (cn < N) {
                atomicAdd(&C[(size_t)r * N + cn], acc[mi][ni][0]);
                atomicAdd(&C[(size_t)(r + 8) * N + cn], acc[mi][ni][2]);
            }
            if (cn + 1 < N) {
                atomicAdd(&C[(size_t)r * N + cn + 1], acc[mi][ni][1]);
                atomicAdd(&C[(size_t)(r + 8) * N + cn + 1], acc[mi][ni][3]);
            }
        }
    }
}

// ---------------- attention softmax + coverage ----------------
__global__ void k_attn_softmax(const float* __restrict__ e, const float* __restrict__ pcov,
                               float* __restrict__ attn, float* __restrict__ covo) {
    int b = blockIdx.x, t = threadIdx.x;
    __shared__ float red[4];
    __shared__ float bval;
    const float* er = e + b * S_;
    float m = -1e30f;
    for (int s = t; s < S_; s += 128) m = fmaxf(m, er[s]);
    for (int o = 16; o; o >>= 1) m = fmaxf(m, __shfl_xor_sync(0xffffffffu, m, o));
    if ((t & 31) == 0) red[t >> 5] = m;
    __syncthreads();
    if (t == 0) bval = fmaxf(fmaxf(red[0], red[1]), fmaxf(red[2], red[3]));
    __syncthreads();
    m = bval;
    float sum = 0.f;
    for (int s = t; s < S_; s += 128) sum += __expf(er[s] - m);
    for (int o = 16; o; o >>= 1) sum += __shfl_xor_sync(0xffffffffu, sum, o);
    if ((t & 31) == 0) red[t >> 5] = sum;
    __syncthreads();
    if (t == 0) bval = red[0] + red[1] + red[2] + red[3];
    __syncthreads();
    float inv = 1.f / bval;
    for (int s = t; s < S_; s += 128) {
        float a = __expf(er[s] - m) * inv;
        attn[b * S_ + s] = a;
        covo[b * S_ + s] = pcov[b * S_ + s] + a;
    }
}

// ---------------- context = attn @ enc_states (fp16 enc, fp32 accum) ----------------
__global__ void k_context(const float* __restrict__ attn, const __half* __restrict__ ench,
                          float* __restrict__ ctx, float* __restrict__ hc) {
    int b = blockIdx.y;
    int d = blockIdx.x * 128 + threadIdx.x;
    const float* ab = attn + b * S_;
    const __half* eb = ench + (size_t)b * S_ * TWOH + d;
    float s = 0.f;
#pragma unroll 4
    for (int j = 0; j < S_; j++) s += ab[j] * __half2float(eb[(size_t)j * TWOH]);
    ctx[b * TWOH + d] = s;
    hc[b * 1536 + 512 + d] = s;
}

// ---------------- p_gen ----------------
__global__ void k_pgen(const float* __restrict__ sh, const float* __restrict__ ctx,
                       const float* __restrict__ x, const float* __restrict__ Wpg,
                       const float* __restrict__ bpg, float* __restrict__ pg) {
    int b = blockIdx.x, t = threadIdx.x;
    __shared__ float red[8];
    float s = 0.f;
    for (int j = t; j < 2176; j += 256) {
        float val = (j < 1024) ? sh[b * TWOH + j]
                  : (j < 2048) ? ctx[b * TWOH + (j - 1024)]
                               : x[b * E_ + (j - 2048)];
        s += val * Wpg[j];
    }
    for (int o = 16; o; o >>= 1) s += __shfl_xor_sync(0xffffffffu, s, o);
    if ((t & 31) == 0) red[t >> 5] = s;
    __syncthreads();
    if (t == 0) {
        float tot = 0.f;
        for (int w = 0; w < 8; w++) tot += red[w];
        pg[b] = fsig(tot + bpg[0]);
    }
}

// ---------------- final scale: fd *= pg/vsum over V columns ----------------
__global__ void k_scale(float* __restrict__ fd, const float* __restrict__ pg,
                        const float* __restrict__ vsum) {
    int idx = blockIdx.x * blockDim.x + threadIdx.x;
    if (idx >= B_ * V_) return;
    int b = idx / V_, col = idx - b * V_;
    float f = pg[b] / vsum[b];
    fd[(size_t)b * VEXT + col] *= f;
}

__global__ void k_scatter(const float* __restrict__ attn, const float* __restrict__ pg,
                          const int* __restrict__ eie, float* __restrict__ fd) {
    int i = blockIdx.x * blockDim.x + threadIdx.x;
    if (i >= B_ * S_) return;
    int b = i / S_;
    float ad = (1.f - pg[b]) * attn[i];
    atomicAdd(&fd[(size_t)b * VEXT + eie[i]], ad);
}

// ---------------- launch ----------------
extern "C" void kernel_launch(void* const* d_in, const int* in_sizes, int n_in,
                              void* d_out, int out_size) {
    int o = (in_sizes[5] == 1) ? 1 : 0;  // oov_nums may be a 1-elem input
    const int*   pt   = (const int*)d_in[0];
    const float* h0   = (const float*)d_in[1];
    const float* c0   = (const float*)d_in[2];
    const float* enc  = (const float*)d_in[3];
    const int*   eie  = (const int*)d_in[4];
    const float* pcv  = (const float*)d_in[5 + o];
    const float* pcov = (const float*)d_in[6 + o];
    const float* emb  = (const float*)d_in[7 + o];
    const float* Wxc  = (const float*)d_in[8 + o];
    const float* bxc  = (const float*)d_in[9 + o];
    const float* Wih  = (const float*)d_in[10 + o];
    const float* Whh  = (const float*)d_in[11 + o];
    const float* bih  = (const float*)d_in[12 + o];
    const float* bhh  = (const float*)d_in[13 + o];
    const float* Wh   = (const float*)d_in[14 + o];
    const float* bh   = (const float*)d_in[15 + o];
    const float* Ws   = (const float*)d_in[16 + o];
    const float* bs   = (const float*)d_in[17 + o];
    const float* Wc   = (const float*)d_in[18 + o];
    const float* bc   = (const float*)d_in[19 + o];
    const float* vv   = (const float*)d_in[20 + o];
    const float* Wv1  = (const float*)d_in[21 + o];
    const float* bv1  = (const float*)d_in[22 + o];
    const float* Wv2  = (const float*)d_in[23 + o];
    const float* bv2  = (const float*)d_in[24 + o];
    const float* Wpg  = (const float*)d_in[25 + o];
    const float* bpg  = (const float*)d_in[26 + o];

    float* sc;
    cudaGetSymbolAddress((void**)&sc, g_scratch);
    __half* hh;
    cudaGetSymbolAddress((void**)&hh, g_half);
    cudaFuncSetAttribute(gemma, cudaFuncAttributeMaxDynamicSharedMemorySize, 2 * GA_BUF);
    cudaFuncSetAttribute(gemml, cudaFuncAttributeMaxDynamicSharedMemorySize, 2 * GA_BUF);

    float* out   = (float*)d_out;
    float* o_fd  = out;                       // 128*50050
    float* o_h   = out + 6406400;             // 128*512
    float* o_c   = o_h + 65536;               // 128*512
    float* o_ctx = o_c + 65536;               // 128*1024
    float* o_at  = o_ctx + 131072;            // 128*400
    float* o_pg  = o_at + 51200;              // 128
    float* o_cov = o_pg + 128;                // 128*400

    float* xbuf = sc + OFF_X;
    float* gbuf = sc + OFF_GATES;
    float* wsh  = sc + OFF_WSH;
    float* ebuf = sc + OFF_E;
    float* vsum = sc + OFF_VSUM;
    __half* ench = hh + HOFF_ENC;
    __half* whh  = hh + HOFF_WH;
    __half* wv2h = hh + HOFF_WV2;
    __half* hidh = hh + HOFF_HID;

    bool fork = g_aux.ok;

    // --- fork: fp16 staging on aux stream, overlapped with the small chain ---
    if (fork) {
        cudaEventRecord(g_aux.e0, 0);
        cudaStreamWaitEvent(g_aux.s, g_aux.e0, 0);
        k_convA<<<(26738688 + 255) / 256, 256, 0, g_aux.s>>>(enc, Wh, hh);
        cudaEventRecord(g_aux.e1, g_aux.s);
        k_convB<<<(12800000 + 255) / 256, 256, 0, g_aux.s>>>(Wv2, hh);
        cudaEventRecord(g_aux.e2, g_aux.s);
    } else {
        k_convA<<<(26738688 + 255) / 256, 256>>>(enc, Wh, hh);
        k_convB<<<(12800000 + 255) / 256, 256>>>(Wv2, hh);
    }

    // --- main stream: prep + small-GEMM chain (independent of staging) ---
    k_prep<<<(680320 + 255) / 256, 256>>>(pt, emb, pcv, bxc, bs, bv1,
                                          sc + OFF_EPC, xbuf, gbuf, wsh, sc + OFF_HID, ebuf,
                                          vsum, o_fd);
    gemm2<<<dim3(1, 1, 12), 256>>>(sc + OFF_EPC, Wxc, xbuf, 128, 128, 1152, 96);
    gemm2<<<dim3(16, 1, 4), 256>>>(xbuf, Wih, gbuf, 128, 2048, 128, 32);
    gemm2<<<dim3(16, 1, 4), 256>>>(h0, Whh, gbuf, 128, 2048, 512, 128);
    k_lstm<<<(B_ * H_ + 255) / 256, 256>>>(gbuf, c0, bih, bhh, o_h, o_c,
                                           sc + OFF_SH, sc + OFF_HC);
    gemm2<<<dim3(8, 1, 8), 256>>>(sc + OFF_SH, Ws, wsh, 128, 1024, 1024, 128);

    // --- join A: gemma needs ench/whh ---
    if (fork) cudaStreamWaitEvent(0, g_aux.e1, 0);
    gemma<<<dim3(4, 400), 512, 2 * GA_BUF>>>(ench, whh, bh, bc, wsh, Wc, vv, pcov, ebuf);

    k_attn_softmax<<<128, 128>>>(ebuf, pcov, o_at, o_cov);
    k_context<<<dim3(8, 128), 128>>>(o_at, ench, o_ctx, sc + OFF_HC);
    gemm2<<<dim3(4, 1, 8), 256>>>(sc + OFF_HC, Wv1, sc + OFF_HID, 128, 512, 1536, 192);
    k_h2<<<(32768 + 255) / 256, 256>>>(sc + OFF_HID, hidh);

    // --- join B: gemml needs wv2h (converted under gemma's shadow) ---
    if (fork) cudaStreamWaitEvent(0, g_aux.e2, 0);
    gemml<<<dim3(196, 1), 512, 2 * GA_BUF>>>(hidh, wv2h, bv2, o_fd, vsum, V_);

    k_pgen<<<128, 256>>>(sc + OFF_SH, o_ctx, xbuf, Wpg, bpg, o_pg);
    k_scale<<<(B_ * V_ + 255) / 256, 256>>>(o_fd, o_pg, vsum);
    k_scatter<<<(B_ * S_ + 255) / 256, 256>>>(o_at, o_pg, eie, o_fd);
}

// round 13
// speedup vs baseline: 1.1081x; 1.1081x over previous
#include <cuda_runtime.h>
#include <cuda_fp16.h>
#include <cstdint>
#include <cstddef>

#define B_   128
#define S_   400
#define H_   512
#define E_   128
#define V_   50000
#define VEXT 50050
#define TWOH 1024

// ---------------- scratch (float offsets) ----------------
#define OFF_EPC    0u          // 128*1152
#define OFF_X      147456u     // 128*128
#define OFF_GATES  163840u     // 128*2048
#define OFF_SH     425984u     // 128*1024  (s_hat = [h,c])
#define OFF_WSH    557056u     // 128*1024  (s_hat@Ws.T + bs)
#define OFF_E      688128u     // 128*400
#define OFF_HC     739328u     // 128*1536  ([h, context])
#define OFF_HID    935936u     // 128*512
#define OFF_VSUM   1001472u    // 128
#define SCRATCH_TOTAL 1001600u

__device__ float g_scratch[SCRATCH_TOTAL];

// fp16 staging: Wh + Wv2 + hid   (enc converted inline in gemma)
#define HOFF_WH  0u            // 1048576
#define HOFF_WV2 1048576u      // 25600000
#define HOFF_HID 26648576u     // 65536
#define HALF_TOTAL 26714112u
__device__ __align__(16) __half g_half[HALF_TOTAL];

// ---------------- helpers ----------------
__device__ __forceinline__ float f2tf32(float x) {
    uint32_t u;
    asm("cvt.rna.tf32.f32 %0, %1;" : "=r"(u) : "f"(x));
    return __uint_as_float(u);
}
__device__ __forceinline__ float fsig(float x) { return 1.0f / (1.0f + __expf(-x)); }
__device__ __forceinline__ float ftanh(float x) { return 1.0f - 2.0f / (1.0f + __expf(2.0f * x)); }

__device__ __forceinline__ uint32_t pack_h2(float a, float b) {
    __half2 h = __floats2half2_rn(a, b);
    return *reinterpret_cast<uint32_t*>(&h);
}

__device__ __forceinline__ uint32_t s2u(const void* p) {
    uint32_t a;
    asm("{ .reg .u64 t; cvta.to.shared.u64 t, %1; cvt.u32.u64 %0, t; }" : "=r"(a) : "l"(p));
    return a;
}

__device__ __forceinline__ void mma_tf32(float* c, const uint32_t* a, uint32_t b0, uint32_t b1) {
    asm volatile(
        "mma.sync.aligned.m16n8k8.row.col.f32.tf32.tf32.f32 "
        "{%0,%1,%2,%3},{%4,%5,%6,%7},{%8,%9},{%0,%1,%2,%3};\n"
        : "+f"(c[0]), "+f"(c[1]), "+f"(c[2]), "+f"(c[3])
        : "r"(a[0]), "r"(a[1]), "r"(a[2]), "r"(a[3]), "r"(b0), "r"(b1));
}

__device__ __forceinline__ void mma_f16(float* c, const uint32_t* a, uint32_t b0, uint32_t b1) {
    asm volatile(
        "mma.sync.aligned.m16n8k16.row.col.f32.f16.f16.f32 "
        "{%0,%1,%2,%3},{%4,%5,%6,%7},{%8,%9},{%0,%1,%2,%3};\n"
        : "+f"(c[0]), "+f"(c[1]), "+f"(c[2]), "+f"(c[3])
        : "r"(a[0]), "r"(a[1]), "r"(a[2]), "r"(a[3]), "r"(b0), "r"(b1));
}

#define LDSM4(r0, r1, r2, r3, addr) \
    asm volatile("ldmatrix.sync.aligned.m8n8.x4.shared.b16 {%0,%1,%2,%3}, [%4];" \
                 : "=r"(r0), "=r"(r1), "=r"(r2), "=r"(r3) : "r"(addr))

__device__ __forceinline__ void cp16(uint32_t dst, const void* src) {
    asm volatile("cp.async.cg.shared.global [%0], [%1], 16;" :: "r"(dst), "l"(src));
}
__device__ __forceinline__ void cp16z(uint32_t dst, const void* src, int sz) {
    asm volatile("cp.async.cg.shared.global [%0], [%1], 16, %2;" :: "r"(dst), "l"(src), "r"(sz));
}
__device__ __forceinline__ void sts128(uint32_t addr, uint32_t a, uint32_t b, uint32_t c, uint32_t d) {
    asm volatile("st.shared.v4.b32 [%0], {%1,%2,%3,%4};" :: "r"(addr), "r"(a), "r"(b), "r"(c), "r"(d));
}

// ---------------- fp32 -> fp16 staging (Wh, Wv2 only) ----------------
__global__ void k_convert(const float* __restrict__ Wh, const float* __restrict__ Wv2,
                          __half* __restrict__ hh) {
    int i = blockIdx.x * blockDim.x + threadIdx.x;
    if (i < 524288) {
        float2 v = ((const float2*)Wh)[i];
        ((__half2*)(hh + HOFF_WH))[i] = __floats2half2_rn(v.x, v.y);
    } else if (i < 13324288) {
        int j = i - 524288;
        float2 v = ((const float2*)Wv2)[j];
        ((__half2*)(hh + HOFF_WV2))[j] = __floats2half2_rn(v.x, v.y);
    }
}

// hid fp32 -> fp16
__global__ void k_h2(const float* __restrict__ hid, __half* __restrict__ hidh) {
    int i = blockIdx.x * blockDim.x + threadIdx.x;
    if (i < 32768) {
        float2 v = ((const float2*)hid)[i];
        ((__half2*)hidh)[i] = __floats2half2_rn(v.x, v.y);
    }
}

// ---------------- fused prep: epc build + bias inits + e zero + vsum/fd-oov zero ----------------
__global__ void k_prep(const int* __restrict__ pt, const float* __restrict__ emb,
                       const float* __restrict__ pcv, const float* __restrict__ bxc,
                       const float* __restrict__ bs, const float* __restrict__ bv1,
                       float* __restrict__ epc, float* __restrict__ xbuf,
                       float* __restrict__ gbuf, float* __restrict__ wsh,
                       float* __restrict__ hid, float* __restrict__ ebuf,
                       float* __restrict__ vsum, float* __restrict__ fd) {
    int i = blockIdx.x * blockDim.x + threadIdx.x;
    if (i < 147456) {
        int b = i / 1152, c = i - b * 1152;
        epc[i] = (c < E_) ? emb[(size_t)pt[b] * E_ + c] : pcv[b * TWOH + (c - E_)];
        return;
    }
    i -= 147456;
    if (i < 16384) { xbuf[i] = bxc[i & 127]; return; }
    i -= 16384;
    if (i < 262144) { gbuf[i] = 0.f; return; }
    i -= 262144;
    if (i < 131072) { wsh[i] = bs[i & 1023]; return; }
    i -= 131072;
    if (i < 65536) { hid[i] = bv1[i & 511]; return; }
    i -= 65536;
    if (i < 51200) { ebuf[i] = 0.f; return; }
    i -= 51200;
    if (i < 128) { vsum[i] = 0.f; return; }
    i -= 128;
    if (i < 6400) {
        int b = i / 50, c = i - b * 50;
        fd[(size_t)b * VEXT + V_ + c] = 0.f;
    }
}

// ---------------- LSTM pointwise ----------------
__global__ void k_lstm(const float* __restrict__ gates, const float* __restrict__ c0,
                       const float* __restrict__ b_ih, const float* __restrict__ b_hh,
                       float* __restrict__ out_h, float* __restrict__ out_c,
                       float* __restrict__ sh, float* __restrict__ hc) {
    int idx = blockIdx.x * blockDim.x + threadIdx.x;
    if (idx >= B_ * H_) return;
    int b = idx >> 9, j = idx & 511;
    const float* gb = gates + b * 2048;
    float gi = gb[j]        + b_ih[j]        + b_hh[j];
    float gf = gb[512 + j]  + b_ih[512 + j]  + b_hh[512 + j];
    float gg = gb[1024 + j] + b_ih[1024 + j] + b_hh[1024 + j];
    float go = gb[1536 + j] + b_ih[1536 + j] + b_hh[1536 + j];
    float c = fsig(gf) * c0[idx] + fsig(gi) * tanhf(gg);
    float h = fsig(go) * tanhf(c);
    out_h[idx] = h;
    out_c[idx] = c;
    sh[b * TWOH + j] = h;
    sh[b * TWOH + H_ + j] = c;
    hc[b * 1536 + j] = h;
}

// ---------------- attention GEMM: fp32 A inline-converted, fp16 B depth-1 cp.async ----------------
// BM=128, BN=256, BK=32, 512 threads (16 warps, warp tile 64x32), grid (4, 400).
// smem: 2 bufs x (A 128x80B + B 256x80B) = 61440 B dynamic.
// Pipeline per iter kb (race-free, mirrors the proven 774us schedule):
//   cp B(kb+1)->buf[(kb+1)&1]; commit; wait 1   (B(kb) complete)
//   STS A(kb) regs->buf[kb&1]                   (buf last read iter kb-2, fenced)
//   __syncthreads                               (A store + B(kb) visible)
//   LDG A(kb+1)->regs                           (latency hidden under compute)
//   compute buf[kb&1]; __syncthreads
#define GA_BUF 30720

__global__ void __launch_bounds__(512)
gemma(const float* __restrict__ Af, const __half* __restrict__ Bh,
      const float* __restrict__ bh, const float* __restrict__ bcv,
      const float* __restrict__ sWs, const float* __restrict__ Wc,
      const float* __restrict__ vv, const float* __restrict__ cov,
      float* __restrict__ eout)
{
    extern __shared__ char sm[];
    uint32_t sbase = s2u(sm);
    int tid = threadIdx.x, lane = tid & 31, warp = tid >> 5;
    int wm = (warp & 1) * 64;
    int wn = (warp >> 1) * 32;
    int bm = blockIdx.y * 128, bn = blockIdx.x * 256;

    float acc[4][4][4];
#pragma unroll
    for (int i = 0; i < 4; i++)
#pragma unroll
        for (int j = 0; j < 4; j++)
#pragma unroll
            for (int l = 0; l < 4; l++) acc[i][j][l] = 0.f;

    int r = tid >> 2, c = tid & 3;
    const float*  Asrc  = Af + (size_t)(bm + r) * 1024 + c * 8;
    const __half* Bsrc0 = Bh + (size_t)(bn + r) * 1024 + c * 8;
    const __half* Bsrc1 = Bh + (size_t)(bn + 128 + r) * 1024 + c * 8;
    uint32_t dA  = sbase + r * 80 + c * 16;
    uint32_t dB0 = sbase + 10240 + r * 80 + c * 16;
    uint32_t dB1 = sbase + 10240 + (128 + r) * 80 + c * 16;

    // prologue: A(0) regs; cp B(0) into buf0
    float4 a0 = *(const float4*)(Asrc);
    float4 a1 = *(const float4*)(Asrc + 4);
    cp16(dB0, Bsrc0); cp16(dB1, Bsrc1);
    asm volatile("cp.async.commit_group;" ::: "memory");

    for (int kb = 0; kb < 32; kb++) {
        if (kb + 1 < 32) {
            int off = ((kb + 1) & 1) * GA_BUF;
            int kof = (kb + 1) * 32;
            cp16(dB0 + off, Bsrc0 + kof);
            cp16(dB1 + off, Bsrc1 + kof);
            asm volatile("cp.async.commit_group;" ::: "memory");
            asm volatile("cp.async.wait_group 1;" ::: "memory");
        } else {
            asm volatile("cp.async.wait_group 0;" ::: "memory");
        }
        uint32_t bo = (kb & 1) * GA_BUF;
        // store A(kb) (fp32 regs -> fp16 smem) into the buffer compute will read
        sts128(dA + bo, pack_h2(a0.x, a0.y), pack_h2(a0.z, a0.w),
                        pack_h2(a1.x, a1.y), pack_h2(a1.z, a1.w));
        __syncthreads();
        if (kb + 1 < 32) {
            int kof = (kb + 1) * 32;
            a0 = *(const float4*)(Asrc + kof);
            a1 = *(const float4*)(Asrc + kof + 4);
        }

        uint32_t arow = sbase + bo + (wm + (lane & 15)) * 80 + ((lane >> 4) << 4);
        uint32_t brow = sbase + bo + 10240 + (wn + (lane & 15)) * 80 + ((lane >> 4) << 4);
#pragma unroll
        for (int st = 0; st < 2; st++) {
            uint32_t kbyt = st * 32;
            uint32_t af[4][4], bf[4][2];
#pragma unroll
            for (int mi = 0; mi < 4; mi++)
                LDSM4(af[mi][0], af[mi][1], af[mi][2], af[mi][3],
                      arow + mi * (16 * 80) + kbyt);
#pragma unroll
            for (int nj = 0; nj < 2; nj++) {
                uint32_t q0, q1, q2, q3;
                LDSM4(q0, q1, q2, q3, brow + nj * (16 * 80) + kbyt);
                bf[nj * 2][0] = q0; bf[nj * 2 + 1][0] = q1;
                bf[nj * 2][1] = q2; bf[nj * 2 + 1][1] = q3;
            }
#pragma unroll
            for (int mi = 0; mi < 4; mi++)
#pragma unroll
                for (int ni = 0; ni < 4; ni++)
                    mma_f16(acc[mi][ni], af[mi], bf[ni][0], bf[ni][1]);
        }
        __syncthreads();
    }

    // fused attention epilogue
#pragma unroll
    for (int mi = 0; mi < 4; mi++) {
        int rr0 = bm + wm + mi * 16 + (lane >> 2);
        int rr1 = rr0 + 8;
        int b0 = rr0 / S_, b1 = rr1 / S_;
        float cv0 = cov[rr0], cv1 = cov[rr1];
        float p0 = 0.f, p1 = 0.f;
#pragma unroll
        for (int ni = 0; ni < 4; ni++) {
#pragma unroll
            for (int j = 0; j < 2; j++) {
                int n = bn + wn + ni * 8 + (lane & 3) * 2 + j;
                float base = bh[n] + bcv[n];
                float wc = Wc[n], vn = vv[n];
                p0 += ftanh(acc[mi][ni][j]     + base + sWs[b0 * TWOH + n] + cv0 * wc) * vn;
                p1 += ftanh(acc[mi][ni][2 + j] + base + sWs[b1 * TWOH + n] + cv1 * wc) * vn;
            }
        }
        p0 += __shfl_xor_sync(0xffffffffu, p0, 1);
        p0 += __shfl_xor_sync(0xffffffffu, p0, 2);
        p1 += __shfl_xor_sync(0xffffffffu, p1, 1);
        p1 += __shfl_xor_sync(0xffffffffu, p1, 2);
        if ((lane & 3) == 0) {
            atomicAdd(&eout[rr0], p0);
            atomicAdd(&eout[rr1], p1);
        }
    }
}

// ---------------- logits GEMM: all-fp16, fused exp + rowsum epilogue ----------------
__global__ void __launch_bounds__(512)
gemml(const __half* __restrict__ Ah, const __half* __restrict__ Bh,
      const float* __restrict__ bias, float* __restrict__ fd,
      float* __restrict__ vsum, int N)
{
    extern __shared__ char sm[];
    uint32_t sbase = s2u(sm);
    int tid = threadIdx.x, lane = tid & 31, warp = tid >> 5;
    int wm = (warp & 1) * 64;
    int wn = (warp >> 1) * 32;
    int bm = blockIdx.y * 128, bn = blockIdx.x * 256;

    float acc[4][4][4];
#pragma unroll
    for (int i = 0; i < 4; i++)
#pragma unroll
        for (int j = 0; j < 4; j++)
#pragma unroll
            for (int l = 0; l < 4; l++) acc[i][j][l] = 0.f;

    int r = tid >> 2, c = tid & 3;
    int n0 = bn + r, n1 = bn + 128 + r;
    int s0 = (n0 < N) ? 16 : 0, s1 = (n1 < N) ? 16 : 0;
    const __half* Asrc  = Ah + (size_t)(bm + r) * 512 + c * 8;
    const __half* Bsrc0 = Bh + (size_t)n0 * 512 + c * 8;
    const __half* Bsrc1 = Bh + (size_t)n1 * 512 + c * 8;
    uint32_t dA  = sbase + r * 80 + c * 16;
    uint32_t dB0 = sbase + 10240 + r * 80 + c * 16;
    uint32_t dB1 = sbase + 10240 + (128 + r) * 80 + c * 16;

    cp16(dA, Asrc); cp16z(dB0, Bsrc0, s0); cp16z(dB1, Bsrc1, s1);
    asm volatile("cp.async.commit_group;" ::: "memory");

    for (int kb = 0; kb < 16; kb++) {
        if (kb + 1 < 16) {
            int off = ((kb + 1) & 1) * GA_BUF;
            int kof = (kb + 1) * 32;
            cp16(dA + off, Asrc + kof);
            cp16z(dB0 + off, Bsrc0 + kof, s0);
            cp16z(dB1 + off, Bsrc1 + kof, s1);
            asm volatile("cp.async.commit_group;" ::: "memory");
            asm volatile("cp.async.wait_group 1;" ::: "memory");
        } else {
            asm volatile("cp.async.wait_group 0;" ::: "memory");
        }
        __syncthreads();

        uint32_t bo = (kb & 1) * GA_BUF;
        uint32_t arow = sbase + bo + (wm + (lane & 15)) * 80 + ((lane >> 4) << 4);
        uint32_t brow = sbase + bo + 10240 + (wn + (lane & 15)) * 80 + ((lane >> 4) << 4);
#pragma unroll
        for (int st = 0; st < 2; st++) {
            uint32_t kbyt = st * 32;
            uint32_t af[4][4], bf[4][2];
#pragma unroll
            for (int mi = 0; mi < 4; mi++)
                LDSM4(af[mi][0], af[mi][1], af[mi][2], af[mi][3],
                      arow + mi * (16 * 80) + kbyt);
#pragma unroll
            for (int nj = 0; nj < 2; nj++) {
                uint32_t q0, q1, q2, q3;
                LDSM4(q0, q1, q2, q3, brow + nj * (16 * 80) + kbyt);
                bf[nj * 2][0] = q0; bf[nj * 2 + 1][0] = q1;
                bf[nj * 2][1] = q2; bf[nj * 2 + 1][1] = q3;
            }
#pragma unroll
            for (int mi = 0; mi < 4; mi++)
#pragma unroll
                for (int ni = 0; ni < 4; ni++)
                    mma_f16(acc[mi][ni], af[mi], bf[ni][0], bf[ni][1]);
        }
        __syncthreads();
    }

    // epilogue: exp(logit) -> fd, quad-reduced row sums -> vsum
#pragma unroll
    for (int mi = 0; mi < 4; mi++) {
        int rr = bm + wm + mi * 16 + (lane >> 2);
        float s0r = 0.f, s1r = 0.f;
#pragma unroll
        for (int ni = 0; ni < 4; ni++) {
            int cn = bn + wn + ni * 8 + (lane & 3) * 2;
#pragma unroll
            for (int j = 0; j < 2; j++) {
                if (cn + j < N) {
                    float bi = bias[cn + j];
                    float e0 = __expf(acc[mi][ni][j] + bi);
                    float e1 = __expf(acc[mi][ni][2 + j] + bi);
                    fd[(size_t)rr * VEXT + cn + j] = e0;
                    fd[(size_t)(rr + 8) * VEXT + cn + j] = e1;
                    s0r += e0;
                    s1r += e1;
                }
            }
        }
        s0r += __shfl_xor_sync(0xffffffffu, s0r, 1);
        s0r += __shfl_xor_sync(0xffffffffu, s0r, 2);
        s1r += __shfl_xor_sync(0xffffffffu, s1r, 1);
        s1r += __shfl_xor_sync(0xffffffffu, s1r, 2);
        if ((lane & 3) == 0) {
            atomicAdd(&vsum[rr], s0r);
            atomicAdd(&vsum[rr + 8], s1r);
        }
    }
}

// ---------------- small tf32 GEMM (mma.sync), split-K accumulate ----------------
#define BM 128
#define BN 128
#define BK 16

__global__ void __launch_bounds__(256)
gemm2(const float* __restrict__ A, const float* __restrict__ W,
      float* __restrict__ C, int M, int N, int K, int Kc)
{
    __shared__ float As[2][BK][BM + 4];
    __shared__ float Bs[2][BK][BN + 4];
    int tid = threadIdx.x;
    int lane = tid & 31, warp = tid >> 5;
    int wm = (warp & 1) * 64;
    int wn = (warp >> 1) * 32;
    int bm = blockIdx.y * BM, bn = blockIdx.x * BN;
    int k0 = blockIdx.z * Kc;
    int kend = k0 + Kc; if (kend > K) kend = K;

    float acc[4][4][4];
#pragma unroll
    for (int i = 0; i < 4; i++)
#pragma unroll
        for (int j = 0; j < 4; j++)
#pragma unroll
            for (int l = 0; l < 4; l++) acc[i][j][l] = 0.f;

    int ar = tid >> 2;
    int ac = (tid & 3) * 4;
    const float* Ap0 = A + (size_t)(bm + ar) * K + k0 + ac;
    const float* Ap1 = Ap0 + (size_t)64 * K;
    int nr0 = bn + ar, nr1 = nr0 + 64;
    const float* Wp0 = W + (size_t)nr0 * K + k0 + ac;
    const float* Wp1 = W + (size_t)nr1 * K + k0 + ac;
    bool vb0 = nr0 < N, vb1 = nr1 < N;

    float4 ra0 = *(const float4*)Ap0;
    float4 ra1 = *(const float4*)Ap1;
    float4 rb0 = vb0 ? *(const float4*)Wp0 : make_float4(0, 0, 0, 0);
    float4 rb1 = vb1 ? *(const float4*)Wp1 : make_float4(0, 0, 0, 0);

    int buf = 0;
    {
        As[0][ac + 0][ar] = f2tf32(ra0.x); As[0][ac + 1][ar] = f2tf32(ra0.y);
        As[0][ac + 2][ar] = f2tf32(ra0.z); As[0][ac + 3][ar] = f2tf32(ra0.w);
        As[0][ac + 0][ar + 64] = f2tf32(ra1.x); As[0][ac + 1][ar + 64] = f2tf32(ra1.y);
        As[0][ac + 2][ar + 64] = f2tf32(ra1.z); As[0][ac + 3][ar + 64] = f2tf32(ra1.w);
        Bs[0][ac + 0][ar] = f2tf32(rb0.x); Bs[0][ac + 1][ar] = f2tf32(rb0.y);
        Bs[0][ac + 2][ar] = f2tf32(rb0.z); Bs[0][ac + 3][ar] = f2tf32(rb0.w);
        Bs[0][ac + 0][ar + 64] = f2tf32(rb1.x); Bs[0][ac + 1][ar + 64] = f2tf32(rb1.y);
        Bs[0][ac + 2][ar + 64] = f2tf32(rb1.z); Bs[0][ac + 3][ar + 64] = f2tf32(rb1.w);
    }
    __syncthreads();

    for (int kk = k0; kk < kend; kk += BK) {
        bool more = (kk + BK) < kend;
        if (more) {
            int d = kk + BK - k0;
            ra0 = *(const float4*)(Ap0 + d);
            ra1 = *(const float4*)(Ap1 + d);
            rb0 = vb0 ? *(const float4*)(Wp0 + d) : make_float4(0, 0, 0, 0);
            rb1 = vb1 ? *(const float4*)(Wp1 + d) : make_float4(0, 0, 0, 0);
        }

#pragma unroll
        for (int ks = 0; ks < BK; ks += 8) {
            uint32_t af[4][4], bf[4][2];
            int kr = ks + (lane & 3);
#pragma unroll
            for (int mi = 0; mi < 4; mi++) {
                int m0 = wm + mi * 16 + (lane >> 2);
                af[mi][0] = __float_as_uint(As[buf][kr][m0]);
                af[mi][1] = __float_as_uint(As[buf][kr][m0 + 8]);
                af[mi][2] = __float_as_uint(As[buf][kr + 4][m0]);
                af[mi][3] = __float_as_uint(As[buf][kr + 4][m0 + 8]);
            }
#pragma unroll
            for (int ni = 0; ni < 4; ni++) {
                int n0 = wn + ni * 8 + (lane >> 2);
                bf[ni][0] = __float_as_uint(Bs[buf][kr][n0]);
                bf[ni][1] = __float_as_uint(Bs[buf][kr + 4][n0]);
            }
#pragma unroll
            for (int mi = 0; mi < 4; mi++)
#pragma unroll
                for (int ni = 0; ni < 4; ni++)
                    mma_tf32(acc[mi][ni], af[mi], bf[ni][0], bf[ni][1]);
        }

        if (more) {
            int nb = buf ^ 1;
            As[nb][ac + 0][ar] = f2tf32(ra0.x); As[nb][ac + 1][ar] = f2tf32(ra0.y);
            As[nb][ac + 2][ar] = f2tf32(ra0.z); As[nb][ac + 3][ar] = f2tf32(ra0.w);
            As[nb][ac + 0][ar + 64] = f2tf32(ra1.x); As[nb][ac + 1][ar + 64] = f2tf32(ra1.y);
            As[nb][ac + 2][ar + 64] = f2tf32(ra1.z); As[nb][ac + 3][ar + 64] = f2tf32(ra1.w);
            Bs[nb][ac + 0][ar] = f2tf32(rb0.x); Bs[nb][ac + 1][ar] = f2tf32(rb0.y);
            Bs[nb][ac + 2][ar] = f2tf32(rb0.z); Bs[nb][ac + 3][ar] = f2tf32(rb0.w);
            Bs[nb][ac + 0][ar + 64] = f2tf32(rb1.x); Bs[nb][ac + 1][ar + 64] = f2tf32(rb1.y);
            Bs[nb][ac + 2][ar + 64] = f2tf32(rb1.z); Bs[nb][ac + 3][ar + 64] = f2tf32(rb1.w);
            __syncthreads();
            buf = nb;
        }
    }

#pragma unroll
    for (int mi = 0; mi < 4; mi++) {
        int r = bm + wm + mi * 16 + (lane >> 2);
#pragma unroll
        for (int ni = 0; ni < 4; ni++) {
            int cn = bn + wn + ni * 8 + (lane & 3) * 2;
            if (cn < N) {
                atomicAdd(&C[(size_t)r * N + cn], acc[mi][ni][0]);
                atomicAdd(&C[(size_t)(r + 8) * N + cn], acc[mi][ni][2]);
            }
            if (cn + 1 < N) {
                atomicAdd(&C[(size_t)r * N + cn + 1], acc[mi][ni][1]);
                atomicAdd(&C[(size_t)(r + 8) * N + cn + 1], acc[mi][ni][3]);
            }
        }
    }
}

// ---------------- attention softmax + coverage ----------------
__global__ void k_attn_softmax(const float* __restrict__ e, const float* __restrict__ pcov,
                               float* __restrict__ attn, float* __restrict__ covo) {
    int b = blockIdx.x, t = threadIdx.x;
    __shared__ float red[4];
    __shared__ float bval;
    const float* er = e + b * S_;
    float m = -1e30f;
    for (int s = t; s < S_; s += 128) m = fmaxf(m, er[s]);
    for (int o = 16; o; o >>= 1) m = fmaxf(m, __shfl_xor_sync(0xffffffffu, m, o));
    if ((t & 31) == 0) red[t >> 5] = m;
    __syncthreads();
    if (t == 0) bval = fmaxf(fmaxf(red[0], red[1]), fmaxf(red[2], red[3]));
    __syncthreads();
    m = bval;
    float sum = 0.f;
    for (int s = t; s < S_; s += 128) sum += __expf(er[s] - m);
    for (int o = 16; o; o >>= 1) sum += __shfl_xor_sync(0xffffffffu, sum, o);
    if ((t & 31) == 0) red[t >> 5] = sum;
    __syncthreads();
    if (t == 0) bval = red[0] + red[1] + red[2] + red[3];
    __syncthreads();
    float inv = 1.f / bval;
    for (int s = t; s < S_; s += 128) {
        float a = __expf(er[s] - m) * inv;
        attn[b * S_ + s] = a;
        covo[b * S_ + s] = pcov[b * S_ + s] + a;
    }
}

// ---------------- context = attn @ enc_states (fp32) ----------------
__global__ void k_context(const float* __restrict__ attn, const float* __restrict__ enc,
                          float* __restrict__ ctx, float* __restrict__ hc) {
    int b = blockIdx.y;
    int d = blockIdx.x * 128 + threadIdx.x;
    const float* ab = attn + b * S_;
    const float* eb = enc + (size_t)b * S_ * TWOH + d;
    float s = 0.f;
#pragma unroll 4
    for (int j = 0; j < S_; j++) s += ab[j] * eb[(size_t)j * TWOH];
    ctx[b * TWOH + d] = s;
    hc[b * 1536 + 512 + d] = s;
}

// ---------------- p_gen ----------------
__global__ void k_pgen(const float* __restrict__ sh, const float* __restrict__ ctx,
                       const float* __restrict__ x, const float* __restrict__ Wpg,
                       const float* __restrict__ bpg, float* __restrict__ pg) {
    int b = blockIdx.x, t = threadIdx.x;
    __shared__ float red[8];
    float s = 0.f;
    for (int j = t; j < 2176; j += 256) {
        float val = (j < 1024) ? sh[b * TWOH + j]
                  : (j < 2048) ? ctx[b * TWOH + (j - 1024)]
                               : x[b * E_ + (j - 2048)];
        s += val * Wpg[j];
    }
    for (int o = 16; o; o >>= 1) s += __shfl_xor_sync(0xffffffffu, s, o);
    if ((t & 31) == 0) red[t >> 5] = s;
    __syncthreads();
    if (t == 0) {
        float tot = 0.f;
        for (int w = 0; w < 8; w++) tot += red[w];
        pg[b] = fsig(tot + bpg[0]);
    }
}

// ---------------- final scale: fd *= pg/vsum over V columns ----------------
__global__ void k_scale(float* __restrict__ fd, const float* __restrict__ pg,
                        const float* __restrict__ vsum) {
    int idx = blockIdx.x * blockDim.x + threadIdx.x;
    if (idx >= B_ * V_) return;
    int b = idx / V_, col = idx - b * V_;
    float f = pg[b] / vsum[b];
    fd[(size_t)b * VEXT + col] *= f;
}

__global__ void k_scatter(const float* __restrict__ attn, const float* __restrict__ pg,
                          const int* __restrict__ eie, float* __restrict__ fd) {
    int i = blockIdx.x * blockDim.x + threadIdx.x;
    if (i >= B_ * S_) return;
    int b = i / S_;
    float ad = (1.f - pg[b]) * attn[i];
    atomicAdd(&fd[(size_t)b * VEXT + eie[i]], ad);
}

// ---------------- launch ----------------
extern "C" void kernel_launch(void* const* d_in, const int* in_sizes, int n_in,
                              void* d_out, int out_size) {
    int o = (in_sizes[5] == 1) ? 1 : 0;  // oov_nums may be a 1-elem input
    const int*   pt   = (const int*)d_in[0];
    const float* h0   = (const float*)d_in[1];
    const float* c0   = (const float*)d_in[2];
    const float* enc  = (const float*)d_in[3];
    const int*   eie  = (const int*)d_in[4];
    const float* pcv  = (const float*)d_in[5 + o];
    const float* pcov = (const float*)d_in[6 + o];
    const float* emb  = (const float*)d_in[7 + o];
    const float* Wxc  = (const float*)d_in[8 + o];
    const float* bxc  = (const float*)d_in[9 + o];
    const float* Wih  = (const float*)d_in[10 + o];
    const float* Whh  = (const float*)d_in[11 + o];
    const float* bih  = (const float*)d_in[12 + o];
    const float* bhh  = (const float*)d_in[13 + o];
    const float* Wh   = (const float*)d_in[14 + o];
    const float* bh   = (const float*)d_in[15 + o];
    const float* Ws   = (const float*)d_in[16 + o];
    const float* bs   = (const float*)d_in[17 + o];
    const float* Wc   = (const float*)d_in[18 + o];
    const float* bc   = (const float*)d_in[19 + o];
    const float* vv   = (const float*)d_in[20 + o];
    const float* Wv1  = (const float*)d_in[21 + o];
    const float* bv1  = (const float*)d_in[22 + o];
    const float* Wv2  = (const float*)d_in[23 + o];
    const float* bv2  = (const float*)d_in[24 + o];
    const float* Wpg  = (const float*)d_in[25 + o];
    const float* bpg  = (const float*)d_in[26 + o];

    float* sc;
    cudaGetSymbolAddress((void**)&sc, g_scratch);
    __half* hh;
    cudaGetSymbolAddress((void**)&hh, g_half);
    cudaFuncSetAttribute(gemma, cudaFuncAttributeMaxDynamicSharedMemorySize, 2 * GA_BUF);
    cudaFuncSetAttribute(gemml, cudaFuncAttributeMaxDynamicSharedMemorySize, 2 * GA_BUF);

    float* out   = (float*)d_out;
    float* o_fd  = out;                       // 128*50050
    float* o_h   = out + 6406400;             // 128*512
    float* o_c   = o_h + 65536;               // 128*512
    float* o_ctx = o_c + 65536;               // 128*1024
    float* o_at  = o_ctx + 131072;            // 128*400
    float* o_pg  = o_at + 51200;              // 128
    float* o_cov = o_pg + 128;                // 128*400

    float* xbuf = sc + OFF_X;
    float* gbuf = sc + OFF_GATES;
    float* wsh  = sc + OFF_WSH;
    float* ebuf = sc + OFF_E;
    float* vsum = sc + OFF_VSUM;
    __half* whh  = hh + HOFF_WH;
    __half* wv2h = hh + HOFF_WV2;
    __half* hidh = hh + HOFF_HID;

    // 1. stage Wh + Wv2 in fp16 (enc converted inline inside gemma)
    k_convert<<<(13324288 + 255) / 256, 256>>>(Wh, Wv2, hh);
    // 2. fused prep (epc build, bias inits, e/vsum/fd-oov zero)
    k_prep<<<(680320 + 255) / 256, 256>>>(pt, emb, pcv, bxc, bs, bv1,
                                          sc + OFF_EPC, xbuf, gbuf, wsh, sc + OFF_HID, ebuf,
                                          vsum, o_fd);
    // 3. x = [emb|pcv] @ Wxc.T + bxc   (split-K 12)
    gemm2<<<dim3(1, 1, 12), 256>>>(sc + OFF_EPC, Wxc, xbuf, 128, 128, 1152, 96);
    // 4. gates = x @ W_ih.T + h0 @ W_hh.T  (split-K 4 each)
    gemm2<<<dim3(16, 1, 4), 256>>>(xbuf, Wih, gbuf, 128, 2048, 128, 32);
    gemm2<<<dim3(16, 1, 4), 256>>>(h0, Whh, gbuf, 128, 2048, 512, 128);
    // 5. LSTM pointwise
    k_lstm<<<(B_ * H_ + 255) / 256, 256>>>(gbuf, c0, bih, bhh, o_h, o_c,
                                           sc + OFF_SH, sc + OFF_HC);
    // 6. sWs = s_hat @ Ws.T + bs  (split-K 8)
    gemm2<<<dim3(8, 1, 8), 256>>>(sc + OFF_SH, Ws, wsh, 128, 1024, 1024, 128);
    // 7. attention logits e (fp32 enc inline-converted, fused epilogue)
    gemma<<<dim3(4, 400), 512, 2 * GA_BUF>>>(enc, whh, bh, bc, wsh, Wc, vv, pcov, ebuf);
    // 8. attn softmax + coverage
    k_attn_softmax<<<128, 128>>>(ebuf, pcov, o_at, o_cov);
    // 9. context (fp32 enc)
    k_context<<<dim3(8, 128), 128>>>(o_at, enc, o_ctx, sc + OFF_HC);
    // 10. hidden = [h|context] @ Wv1.T + bv1  (split-K 8)
    gemm2<<<dim3(4, 1, 8), 256>>>(sc + OFF_HC, Wv1, sc + OFF_HID, 128, 512, 1536, 192);
    // 11. hid -> fp16; exp-logits -> fd + row sums (fused softmax)
    k_h2<<<(32768 + 255) / 256, 256>>>(sc + OFF_HID, hidh);
    gemml<<<dim3(196, 1), 512, 2 * GA_BUF>>>(hidh, wv2h, bv2, o_fd, vsum, V_);
    // 12. p_gen
    k_pgen<<<128, 256>>>(sc + OFF_SH, o_ctx, xbuf, Wpg, bpg, o_pg);
    // 13. scale + pointer scatter
    k_scale<<<(B_ * V_ + 255) / 256, 256>>>(o_fd, o_pg, vsum);
    k_scatter<<<(B_ * S_ + 255) / 256, 256>>>(o_at, o_pg, eie, o_fd);
}

// round 14
// speedup vs baseline: 1.1634x; 1.0499x over previous
#include <cuda_runtime.h>
#include <cuda_fp16.h>
#include <cstdint>
#include <cstddef>

#define B_   128
#define S_   400
#define H_   512
#define E_   128
#define V_   50000
#define VEXT 50050
#define TWOH 1024

// ---------------- scratch (float offsets) ----------------
#define OFF_EPC    0u          // 128*1152
#define OFF_X      147456u     // 128*128
#define OFF_GATES  163840u     // 128*2048
#define OFF_SH     425984u     // 128*1024  (s_hat = [h,c])
#define OFF_WSH    557056u     // 128*1024  (s_hat@Ws.T + bs)
#define OFF_E      688128u     // 128*400
#define OFF_HC     739328u     // 128*1536  ([h, context])
#define OFF_HID    935936u     // 128*512
#define OFF_VSUM   1001472u    // 128
#define SCRATCH_TOTAL 1001600u

__device__ float g_scratch[SCRATCH_TOTAL];

// fp16 staging: Wh + hid   (enc and Wv2 converted inline in the GEMMs)
#define HOFF_WH  0u            // 1048576
#define HOFF_HID 1048576u      // 65536
#define HALF_TOTAL 1114112u
__device__ __align__(16) __half g_half[HALF_TOTAL];

// ---------------- helpers ----------------
__device__ __forceinline__ float f2tf32(float x) {
    uint32_t u;
    asm("cvt.rna.tf32.f32 %0, %1;" : "=r"(u) : "f"(x));
    return __uint_as_float(u);
}
__device__ __forceinline__ float fsig(float x) { return 1.0f / (1.0f + __expf(-x)); }
__device__ __forceinline__ float ftanh(float x) { return 1.0f - 2.0f / (1.0f + __expf(2.0f * x)); }

__device__ __forceinline__ uint32_t pack_h2(float a, float b) {
    __half2 h = __floats2half2_rn(a, b);
    return *reinterpret_cast<uint32_t*>(&h);
}

__device__ __forceinline__ uint32_t s2u(const void* p) {
    uint32_t a;
    asm("{ .reg .u64 t; cvta.to.shared.u64 t, %1; cvt.u32.u64 %0, t; }" : "=r"(a) : "l"(p));
    return a;
}

__device__ __forceinline__ void mma_tf32(float* c, const uint32_t* a, uint32_t b0, uint32_t b1) {
    asm volatile(
        "mma.sync.aligned.m16n8k8.row.col.f32.tf32.tf32.f32 "
        "{%0,%1,%2,%3},{%4,%5,%6,%7},{%8,%9},{%0,%1,%2,%3};\n"
        : "+f"(c[0]), "+f"(c[1]), "+f"(c[2]), "+f"(c[3])
        : "r"(a[0]), "r"(a[1]), "r"(a[2]), "r"(a[3]), "r"(b0), "r"(b1));
}

__device__ __forceinline__ void mma_f16(float* c, const uint32_t* a, uint32_t b0, uint32_t b1) {
    asm volatile(
        "mma.sync.aligned.m16n8k16.row.col.f32.f16.f16.f32 "
        "{%0,%1,%2,%3},{%4,%5,%6,%7},{%8,%9},{%0,%1,%2,%3};\n"
        : "+f"(c[0]), "+f"(c[1]), "+f"(c[2]), "+f"(c[3])
        : "r"(a[0]), "r"(a[1]), "r"(a[2]), "r"(a[3]), "r"(b0), "r"(b1));
}

#define LDSM4(r0, r1, r2, r3, addr) \
    asm volatile("ldmatrix.sync.aligned.m8n8.x4.shared.b16 {%0,%1,%2,%3}, [%4];" \
                 : "=r"(r0), "=r"(r1), "=r"(r2), "=r"(r3) : "r"(addr))

__device__ __forceinline__ void cp16(uint32_t dst, const void* src) {
    asm volatile("cp.async.cg.shared.global [%0], [%1], 16;" :: "r"(dst), "l"(src));
}
__device__ __forceinline__ void sts128(uint32_t addr, uint32_t a, uint32_t b, uint32_t c, uint32_t d) {
    asm volatile("st.shared.v4.b32 [%0], {%1,%2,%3,%4};" :: "r"(addr), "r"(a), "r"(b), "r"(c), "r"(d));
}

// hid fp32 -> fp16
__global__ void k_h2(const float* __restrict__ hid, __half* __restrict__ hidh) {
    int i = blockIdx.x * blockDim.x + threadIdx.x;
    if (i < 32768) {
        float2 v = ((const float2*)hid)[i];
        ((__half2*)hidh)[i] = __floats2half2_rn(v.x, v.y);
    }
}

// ---------------- fused prep: Wh convert + epc build + bias inits + zeros ----------------
__global__ void k_prep(const float* __restrict__ Wh, __half* __restrict__ whh,
                       const int* __restrict__ pt, const float* __restrict__ emb,
                       const float* __restrict__ pcv, const float* __restrict__ bxc,
                       const float* __restrict__ bs, const float* __restrict__ bv1,
                       float* __restrict__ epc, float* __restrict__ xbuf,
                       float* __restrict__ gbuf, float* __restrict__ wsh,
                       float* __restrict__ hid, float* __restrict__ ebuf,
                       float* __restrict__ vsum, float* __restrict__ fd) {
    int i = blockIdx.x * blockDim.x + threadIdx.x;
    if (i < 524288) {
        float2 v = ((const float2*)Wh)[i];
        ((__half2*)whh)[i] = __floats2half2_rn(v.x, v.y);
        return;
    }
    i -= 524288;
    if (i < 147456) {
        int b = i / 1152, c = i - b * 1152;
        epc[i] = (c < E_) ? emb[(size_t)pt[b] * E_ + c] : pcv[b * TWOH + (c - E_)];
        return;
    }
    i -= 147456;
    if (i < 16384) { xbuf[i] = bxc[i & 127]; return; }
    i -= 16384;
    if (i < 262144) { gbuf[i] = 0.f; return; }
    i -= 262144;
    if (i < 131072) { wsh[i] = bs[i & 1023]; return; }
    i -= 131072;
    if (i < 65536) { hid[i] = bv1[i & 511]; return; }
    i -= 65536;
    if (i < 51200) { ebuf[i] = 0.f; return; }
    i -= 51200;
    if (i < 128) { vsum[i] = 0.f; return; }
    i -= 128;
    if (i < 6400) {
        int b = i / 50, c = i - b * 50;
        fd[(size_t)b * VEXT + V_ + c] = 0.f;
    }
}
#define PREP_TOTAL 1204608

// ---------------- LSTM pointwise ----------------
__global__ void k_lstm(const float* __restrict__ gates, const float* __restrict__ c0,
                       const float* __restrict__ b_ih, const float* __restrict__ b_hh,
                       float* __restrict__ out_h, float* __restrict__ out_c,
                       float* __restrict__ sh, float* __restrict__ hc) {
    int idx = blockIdx.x * blockDim.x + threadIdx.x;
    if (idx >= B_ * H_) return;
    int b = idx >> 9, j = idx & 511;
    const float* gb = gates + b * 2048;
    float gi = gb[j]        + b_ih[j]        + b_hh[j];
    float gf = gb[512 + j]  + b_ih[512 + j]  + b_hh[512 + j];
    float gg = gb[1024 + j] + b_ih[1024 + j] + b_hh[1024 + j];
    float go = gb[1536 + j] + b_ih[1536 + j] + b_hh[1536 + j];
    float c = fsig(gf) * c0[idx] + fsig(gi) * tanhf(gg);
    float h = fsig(go) * tanhf(c);
    out_h[idx] = h;
    out_c[idx] = c;
    sh[b * TWOH + j] = h;
    sh[b * TWOH + H_ + j] = c;
    hc[b * 1536 + j] = h;
}

// ---------------- attention GEMM: fp32 A inline-converted, fp16 B depth-1 cp.async ----------------
// (UNCHANGED from the passing 705us kernel)
#define GA_BUF 30720

__global__ void __launch_bounds__(512)
gemma(const float* __restrict__ Af, const __half* __restrict__ Bh,
      const float* __restrict__ bh, const float* __restrict__ bcv,
      const float* __restrict__ sWs, const float* __restrict__ Wc,
      const float* __restrict__ vv, const float* __restrict__ cov,
      float* __restrict__ eout)
{
    extern __shared__ char sm[];
    uint32_t sbase = s2u(sm);
    int tid = threadIdx.x, lane = tid & 31, warp = tid >> 5;
    int wm = (warp & 1) * 64;
    int wn = (warp >> 1) * 32;
    int bm = blockIdx.y * 128, bn = blockIdx.x * 256;

    float acc[4][4][4];
#pragma unroll
    for (int i = 0; i < 4; i++)
#pragma unroll
        for (int j = 0; j < 4; j++)
#pragma unroll
            for (int l = 0; l < 4; l++) acc[i][j][l] = 0.f;

    int r = tid >> 2, c = tid & 3;
    const float*  Asrc  = Af + (size_t)(bm + r) * 1024 + c * 8;
    const __half* Bsrc0 = Bh + (size_t)(bn + r) * 1024 + c * 8;
    const __half* Bsrc1 = Bh + (size_t)(bn + 128 + r) * 1024 + c * 8;
    uint32_t dA  = sbase + r * 80 + c * 16;
    uint32_t dB0 = sbase + 10240 + r * 80 + c * 16;
    uint32_t dB1 = sbase + 10240 + (128 + r) * 80 + c * 16;

    float4 a0 = *(const float4*)(Asrc);
    float4 a1 = *(const float4*)(Asrc + 4);
    cp16(dB0, Bsrc0); cp16(dB1, Bsrc1);
    asm volatile("cp.async.commit_group;" ::: "memory");

    for (int kb = 0; kb < 32; kb++) {
        if (kb + 1 < 32) {
            int off = ((kb + 1) & 1) * GA_BUF;
            int kof = (kb + 1) * 32;
            cp16(dB0 + off, Bsrc0 + kof);
            cp16(dB1 + off, Bsrc1 + kof);
            asm volatile("cp.async.commit_group;" ::: "memory");
            asm volatile("cp.async.wait_group 1;" ::: "memory");
        } else {
            asm volatile("cp.async.wait_group 0;" ::: "memory");
        }
        uint32_t bo = (kb & 1) * GA_BUF;
        sts128(dA + bo, pack_h2(a0.x, a0.y), pack_h2(a0.z, a0.w),
                        pack_h2(a1.x, a1.y), pack_h2(a1.z, a1.w));
        __syncthreads();
        if (kb + 1 < 32) {
            int kof = (kb + 1) * 32;
            a0 = *(const float4*)(Asrc + kof);
            a1 = *(const float4*)(Asrc + kof + 4);
        }

        uint32_t arow = sbase + bo + (wm + (lane & 15)) * 80 + ((lane >> 4) << 4);
        uint32_t brow = sbase + bo + 10240 + (wn + (lane & 15)) * 80 + ((lane >> 4) << 4);
#pragma unroll
        for (int st = 0; st < 2; st++) {
            uint32_t kbyt = st * 32;
            uint32_t af[4][4], bf[4][2];
#pragma unroll
            for (int mi = 0; mi < 4; mi++)
                LDSM4(af[mi][0], af[mi][1], af[mi][2], af[mi][3],
                      arow + mi * (16 * 80) + kbyt);
#pragma unroll
            for (int nj = 0; nj < 2; nj++) {
                uint32_t q0, q1, q2, q3;
                LDSM4(q0, q1, q2, q3, brow + nj * (16 * 80) + kbyt);
                bf[nj * 2][0] = q0; bf[nj * 2 + 1][0] = q1;
                bf[nj * 2][1] = q2; bf[nj * 2 + 1][1] = q3;
            }
#pragma unroll
            for (int mi = 0; mi < 4; mi++)
#pragma unroll
                for (int ni = 0; ni < 4; ni++)
                    mma_f16(acc[mi][ni], af[mi], bf[ni][0], bf[ni][1]);
        }
        __syncthreads();
    }

    // fused attention epilogue
#pragma unroll
    for (int mi = 0; mi < 4; mi++) {
        int rr0 = bm + wm + mi * 16 + (lane >> 2);
        int rr1 = rr0 + 8;
        int b0 = rr0 / S_, b1 = rr1 / S_;
        float cv0 = cov[rr0], cv1 = cov[rr1];
        float p0 = 0.f, p1 = 0.f;
#pragma unroll
        for (int ni = 0; ni < 4; ni++) {
#pragma unroll
            for (int j = 0; j < 2; j++) {
                int n = bn + wn + ni * 8 + (lane & 3) * 2 + j;
                float base = bh[n] + bcv[n];
                float wc = Wc[n], vn = vv[n];
                p0 += ftanh(acc[mi][ni][j]     + base + sWs[b0 * TWOH + n] + cv0 * wc) * vn;
                p1 += ftanh(acc[mi][ni][2 + j] + base + sWs[b1 * TWOH + n] + cv1 * wc) * vn;
            }
        }
        p0 += __shfl_xor_sync(0xffffffffu, p0, 1);
        p0 += __shfl_xor_sync(0xffffffffu, p0, 2);
        p1 += __shfl_xor_sync(0xffffffffu, p1, 1);
        p1 += __shfl_xor_sync(0xffffffffu, p1, 2);
        if ((lane & 3) == 0) {
            atomicAdd(&eout[rr0], p0);
            atomicAdd(&eout[rr1], p1);
        }
    }
}

// ---------------- logits GEMM: fp16 A cp.async, fp32 B inline-converted ----------------
// fd[b, n] = exp(hidh@Wv2.T + bv2); vsum[b] += row sums. grid (196,1), 512 thr.
// Same depth-1 schedule as gemma with A/B roles swapped (Wv2 read once -> no staging).
__global__ void __launch_bounds__(512)
gemml(const __half* __restrict__ Ah, const float* __restrict__ Bf,
      const float* __restrict__ bias, float* __restrict__ fd,
      float* __restrict__ vsum, int N)
{
    extern __shared__ char sm[];
    uint32_t sbase = s2u(sm);
    int tid = threadIdx.x, lane = tid & 31, warp = tid >> 5;
    int wm = (warp & 1) * 64;
    int wn = (warp >> 1) * 32;
    int bm = blockIdx.y * 128, bn = blockIdx.x * 256;

    float acc[4][4][4];
#pragma unroll
    for (int i = 0; i < 4; i++)
#pragma unroll
        for (int j = 0; j < 4; j++)
#pragma unroll
            for (int l = 0; l < 4; l++) acc[i][j][l] = 0.f;

    int r = tid >> 2, c = tid & 3;
    int n0 = bn + r, n1 = bn + 128 + r;
    bool v0 = n0 < N, v1 = n1 < N;
    const __half* Asrc  = Ah + (size_t)(bm + r) * 512 + c * 8;
    const float*  Bsrc0 = Bf + (size_t)n0 * 512 + c * 8;
    const float*  Bsrc1 = Bf + (size_t)n1 * 512 + c * 8;
    uint32_t dA  = sbase + r * 80 + c * 16;
    uint32_t dB0 = sbase + 10240 + r * 80 + c * 16;
    uint32_t dB1 = sbase + 10240 + (128 + r) * 80 + c * 16;

    const float4 Z = make_float4(0, 0, 0, 0);
    // prologue: B(0) regs; cp A(0)
    float4 b00 = v0 ? *(const float4*)(Bsrc0)     : Z;
    float4 b01 = v0 ? *(const float4*)(Bsrc0 + 4) : Z;
    float4 b10 = v1 ? *(const float4*)(Bsrc1)     : Z;
    float4 b11 = v1 ? *(const float4*)(Bsrc1 + 4) : Z;
    cp16(dA, Asrc);
    asm volatile("cp.async.commit_group;" ::: "memory");

    for (int kb = 0; kb < 16; kb++) {
        if (kb + 1 < 16) {
            int off = ((kb + 1) & 1) * GA_BUF;
            int kof = (kb + 1) * 32;
            cp16(dA + off, Asrc + kof);
            asm volatile("cp.async.commit_group;" ::: "memory");
            asm volatile("cp.async.wait_group 1;" ::: "memory");
        } else {
            asm volatile("cp.async.wait_group 0;" ::: "memory");
        }
        uint32_t bo = (kb & 1) * GA_BUF;
        sts128(dB0 + bo, pack_h2(b00.x, b00.y), pack_h2(b00.z, b00.w),
                         pack_h2(b01.x, b01.y), pack_h2(b01.z, b01.w));
        sts128(dB1 + bo, pack_h2(b10.x, b10.y), pack_h2(b10.z, b10.w),
                         pack_h2(b11.x, b11.y), pack_h2(b11.z, b11.w));
        __syncthreads();
        if (kb + 1 < 16) {
            int kof = (kb + 1) * 32;
            b00 = v0 ? *(const float4*)(Bsrc0 + kof)     : Z;
            b01 = v0 ? *(const float4*)(Bsrc0 + kof + 4) : Z;
            b10 = v1 ? *(const float4*)(Bsrc1 + kof)     : Z;
            b11 = v1 ? *(const float4*)(Bsrc1 + kof + 4) : Z;
        }

        uint32_t arow = sbase + bo + (wm + (lane & 15)) * 80 + ((lane >> 4) << 4);
        uint32_t brow = sbase + bo + 10240 + (wn + (lane & 15)) * 80 + ((lane >> 4) << 4);
#pragma unroll
        for (int st = 0; st < 2; st++) {
            uint32_t kbyt = st * 32;
            uint32_t af[4][4], bf[4][2];
#pragma unroll
            for (int mi = 0; mi < 4; mi++)
                LDSM4(af[mi][0], af[mi][1], af[mi][2], af[mi][3],
                      arow + mi * (16 * 80) + kbyt);
#pragma unroll
            for (int nj = 0; nj < 2; nj++) {
                uint32_t q0, q1, q2, q3;
                LDSM4(q0, q1, q2, q3, brow + nj * (16 * 80) + kbyt);
                bf[nj * 2][0] = q0; bf[nj * 2 + 1][0] = q1;
                bf[nj * 2][1] = q2; bf[nj * 2 + 1][1] = q3;
            }
#pragma unroll
            for (int mi = 0; mi < 4; mi++)
#pragma unroll
                for (int ni = 0; ni < 4; ni++)
                    mma_f16(acc[mi][ni], af[mi], bf[ni][0], bf[ni][1]);
        }
        __syncthreads();
    }

    // epilogue: exp(logit) -> fd, quad-reduced row sums -> vsum
#pragma unroll
    for (int mi = 0; mi < 4; mi++) {
        int rr = bm + wm + mi * 16 + (lane >> 2);
        float s0r = 0.f, s1r = 0.f;
#pragma unroll
        for (int ni = 0; ni < 4; ni++) {
            int cn = bn + wn + ni * 8 + (lane & 3) * 2;
#pragma unroll
            for (int j = 0; j < 2; j++) {
                if (cn + j < N) {
                    float bi = bias[cn + j];
                    float e0 = __expf(acc[mi][ni][j] + bi);
                    float e1 = __expf(acc[mi][ni][2 + j] + bi);
                    fd[(size_t)rr * VEXT + cn + j] = e0;
                    fd[(size_t)(rr + 8) * VEXT + cn + j] = e1;
                    s0r += e0;
                    s1r += e1;
                }
            }
        }
        s0r += __shfl_xor_sync(0xffffffffu, s0r, 1);
        s0r += __shfl_xor_sync(0xffffffffu, s0r, 2);
        s1r += __shfl_xor_sync(0xffffffffu, s1r, 1);
        s1r += __shfl_xor_sync(0xffffffffu, s1r, 2);
        if ((lane & 3) == 0) {
            atomicAdd(&vsum[rr], s0r);
            atomicAdd(&vsum[rr + 8], s1r);
        }
    }
}

// ---------------- small tf32 GEMM (mma.sync), split-K accumulate ----------------
#define BM 128
#define BN 128
#define BK 16

__global__ void __launch_bounds__(256)
gemm2(const float* __restrict__ A, const float* __restrict__ W,
      float* __restrict__ C, int M, int N, int K, int Kc)
{
    __shared__ float As[2][BK][BM + 4];
    __shared__ float Bs[2][BK][BN + 4];
    int tid = threadIdx.x;
    int lane = tid & 31, warp = tid >> 5;
    int wm = (warp & 1) * 64;
    int wn = (warp >> 1) * 32;
    int bm = blockIdx.y * BM, bn = blockIdx.x * BN;
    int k0 = blockIdx.z * Kc;
    int kend = k0 + Kc; if (kend > K) kend = K;

    float acc[4][4][4];
#pragma unroll
    for (int i = 0; i < 4; i++)
#pragma unroll
        for (int j = 0; j < 4; j++)
#pragma unroll
            for (int l = 0; l < 4; l++) acc[i][j][l] = 0.f;

    int ar = tid >> 2;
    int ac = (tid & 3) * 4;
    const float* Ap0 = A + (size_t)(bm + ar) * K + k0 + ac;
    const float* Ap1 = Ap0 + (size_t)64 * K;
    int nr0 = bn + ar, nr1 = nr0 + 64;
    const float* Wp0 = W + (size_t)nr0 * K + k0 + ac;
    const float* Wp1 = W + (size_t)nr1 * K + k0 + ac;
    bool vb0 = nr0 < N, vb1 = nr1 < N;

    float4 ra0 = *(const float4*)Ap0;
    float4 ra1 = *(const float4*)Ap1;
    float4 rb0 = vb0 ? *(const float4*)Wp0 : make_float4(0, 0, 0, 0);
    float4 rb1 = vb1 ? *(const float4*)Wp1 : make_float4(0, 0, 0, 0);

    int buf = 0;
    {
        As[0][ac + 0][ar] = f2tf32(ra0.x); As[0][ac + 1][ar] = f2tf32(ra0.y);
        As[0][ac + 2][ar] = f2tf32(ra0.z); As[0][ac + 3][ar] = f2tf32(ra0.w);
        As[0][ac + 0][ar + 64] = f2tf32(ra1.x); As[0][ac + 1][ar + 64] = f2tf32(ra1.y);
        As[0][ac + 2][ar + 64] = f2tf32(ra1.z); As[0][ac + 3][ar + 64] = f2tf32(ra1.w);
        Bs[0][ac + 0][ar] = f2tf32(rb0.x); Bs[0][ac + 1][ar] = f2tf32(rb0.y);
        Bs[0][ac + 2][ar] = f2tf32(rb0.z); Bs[0][ac + 3][ar] = f2tf32(rb0.w);
        Bs[0][ac + 0][ar + 64] = f2tf32(rb1.x); Bs[0][ac + 1][ar + 64] = f2tf32(rb1.y);
        Bs[0][ac + 2][ar + 64] = f2tf32(rb1.z); Bs[0][ac + 3][ar + 64] = f2tf32(rb1.w);
    }
    __syncthreads();

    for (int kk = k0; kk < kend; kk += BK) {
        bool more = (kk + BK) < kend;
        if (more) {
            int d = kk + BK - k0;
            ra0 = *(const float4*)(Ap0 + d);
            ra1 = *(const float4*)(Ap1 + d);
            rb0 = vb0 ? *(const float4*)(Wp0 + d) : make_float4(0, 0, 0, 0);
            rb1 = vb1 ? *(const float4*)(Wp1 + d) : make_float4(0, 0, 0, 0);
        }

#pragma unroll
        for (int ks = 0; ks < BK; ks += 8) {
            uint32_t af[4][4], bf[4][2];
            int kr = ks + (lane & 3);
#pragma unroll
            for (int mi = 0; mi < 4; mi++) {
                int m0 = wm + mi * 16 + (lane >> 2);
                af[mi][0] = __float_as_uint(As[buf][kr][m0]);
                af[mi][1] = __float_as_uint(As[buf][kr][m0 + 8]);
                af[mi][2] = __float_as_uint(As[buf][kr + 4][m0]);
                af[mi][3] = __float_as_uint(As[buf][kr + 4][m0 + 8]);
            }
#pragma unroll
            for (int ni = 0; ni < 4; ni++) {
                int n0 = wn + ni * 8 + (lane >> 2);
                bf[ni][0] = __float_as_uint(Bs[buf][kr][n0]);
                bf[ni][1] = __float_as_uint(Bs[buf][kr + 4][n0]);
            }
#pragma unroll
            for (int mi = 0; mi < 4; mi++)
#pragma unroll
                for (int ni = 0; ni < 4; ni++)
                    mma_tf32(acc[mi][ni], af[mi], bf[ni][0], bf[ni][1]);
        }

        if (more) {
            int nb = buf ^ 1;
            As[nb][ac + 0][ar] = f2tf32(ra0.x); As[nb][ac + 1][ar] = f2tf32(ra0.y);
            As[nb][ac + 2][ar] = f2tf32(ra0.z); As[nb][ac + 3][ar] = f2tf32(ra0.w);
            As[nb][ac + 0][ar + 64] = f2tf32(ra1.x); As[nb][ac + 1][ar + 64] = f2tf32(ra1.y);
            As[nb][ac + 2][ar + 64] = f2tf32(ra1.z); As[nb][ac + 3][ar + 64] = f2tf32(ra1.w);
            Bs[nb][ac + 0][ar] = f2tf32(rb0.x); Bs[nb][ac + 1][ar] = f2tf32(rb0.y);
            Bs[nb][ac + 2][ar] = f2tf32(rb0.z); Bs[nb][ac + 3][ar] = f2tf32(rb0.w);
            Bs[nb][ac + 0][ar + 64] = f2tf32(rb1.x); Bs[nb][ac + 1][ar + 64] = f2tf32(rb1.y);
            Bs[nb][ac + 2][ar + 64] = f2tf32(rb1.z); Bs[nb][ac + 3][ar + 64] = f2tf32(rb1.w);
            __syncthreads();
            buf = nb;
        }
    }

#pragma unroll
    for (int mi = 0; mi < 4; mi++) {
        int r = bm + wm + mi * 16 + (lane >> 2);
#pragma unroll
        for (int ni = 0; ni < 4; ni++) {
            int cn = bn + wn + ni * 8 + (lane & 3) * 2;
            if (cn < N) {
                atomicAdd(&C[(size_t)r * N + cn], acc[mi][ni][0]);
                atomicAdd(&C[(size_t)(r + 8) * N + cn], acc[mi][ni][2]);
            }
            if (cn + 1 < N) {
                atomicAdd(&C[(size_t)r * N + cn + 1], acc[mi][ni][1]);
                atomicAdd(&C[(size_t)(r + 8) * N + cn + 1], acc[mi][ni][3]);
            }
        }
    }
}

// ---------------- attention softmax + coverage ----------------
__global__ void k_attn_softmax(const float* __restrict__ e, const float* __restrict__ pcov,
                               float* __restrict__ attn, float* __restrict__ covo) {
    int b = blockIdx.x, t = threadIdx.x;
    __shared__ float red[4];
    __shared__ float bval;
    const float* er = e + b * S_;
    float m = -1e30f;
    for (int s = t; s < S_; s += 128) m = fmaxf(m, er[s]);
    for (int o = 16; o; o >>= 1) m = fmaxf(m, __shfl_xor_sync(0xffffffffu, m, o));
    if ((t & 31) == 0) red[t >> 5] = m;
    __syncthreads();
    if (t == 0) bval = fmaxf(fmaxf(red[0], red[1]), fmaxf(red[2], red[3]));
    __syncthreads();
    m = bval;
    float sum = 0.f;
    for (int s = t; s < S_; s += 128) sum += __expf(er[s] - m);
    for (int o = 16; o; o >>= 1) sum += __shfl_xor_sync(0xffffffffu, sum, o);
    if ((t & 31) == 0) red[t >> 5] = sum;
    __syncthreads();
    if (t == 0) bval = red[0] + red[1] + red[2] + red[3];
    __syncthreads();
    float inv = 1.f / bval;
    for (int s = t; s < S_; s += 128) {
        float a = __expf(er[s] - m) * inv;
        attn[b * S_ + s] = a;
        covo[b * S_ + s] = pcov[b * S_ + s] + a;
    }
}

// ---------------- context = attn @ enc_states (fp32) ----------------
__global__ void k_context(const float* __restrict__ attn, const float* __restrict__ enc,
                          float* __restrict__ ctx, float* __restrict__ hc) {
    int b = blockIdx.y;
    int d = blockIdx.x * 128 + threadIdx.x;
    const float* ab = attn + b * S_;
    const float* eb = enc + (size_t)b * S_ * TWOH + d;
    float s = 0.f;
#pragma unroll 4
    for (int j = 0; j < S_; j++) s += ab[j] * eb[(size_t)j * TWOH];
    ctx[b * TWOH + d] = s;
    hc[b * 1536 + 512 + d] = s;
}

// ---------------- p_gen ----------------
__global__ void k_pgen(const float* __restrict__ sh, const float* __restrict__ ctx,
                       const float* __restrict__ x, const float* __restrict__ Wpg,
                       const float* __restrict__ bpg, float* __restrict__ pg) {
    int b = blockIdx.x, t = threadIdx.x;
    __shared__ float red[8];
    float s = 0.f;
    for (int j = t; j < 2176; j += 256) {
        float val = (j < 1024) ? sh[b * TWOH + j]
                  : (j < 2048) ? ctx[b * TWOH + (j - 1024)]
                               : x[b * E_ + (j - 2048)];
        s += val * Wpg[j];
    }
    for (int o = 16; o; o >>= 1) s += __shfl_xor_sync(0xffffffffu, s, o);
    if ((t & 31) == 0) red[t >> 5] = s;
    __syncthreads();
    if (t == 0) {
        float tot = 0.f;
        for (int w = 0; w < 8; w++) tot += red[w];
        pg[b] = fsig(tot + bpg[0]);
    }
}

// ---------------- final scale: fd *= pg/vsum over V columns ----------------
__global__ void k_scale(float* __restrict__ fd, const float* __restrict__ pg,
                        const float* __restrict__ vsum) {
    int idx = blockIdx.x * blockDim.x + threadIdx.x;
    if (idx >= B_ * V_) return;
    int b = idx / V_, col = idx - b * V_;
    float f = pg[b] / vsum[b];
    fd[(size_t)b * VEXT + col] *= f;
}

__global__ void k_scatter(const float* __restrict__ attn, const float* __restrict__ pg,
                          const int* __restrict__ eie, float* __restrict__ fd) {
    int i = blockIdx.x * blockDim.x + threadIdx.x;
    if (i >= B_ * S_) return;
    int b = i / S_;
    float ad = (1.f - pg[b]) * attn[i];
    atomicAdd(&fd[(size_t)b * VEXT + eie[i]], ad);
}

// ---------------- launch ----------------
extern "C" void kernel_launch(void* const* d_in, const int* in_sizes, int n_in,
                              void* d_out, int out_size) {
    int o = (in_sizes[5] == 1) ? 1 : 0;  // oov_nums may be a 1-elem input
    const int*   pt   = (const int*)d_in[0];
    const float* h0   = (const float*)d_in[1];
    const float* c0   = (const float*)d_in[2];
    const float* enc  = (const float*)d_in[3];
    const int*   eie  = (const int*)d_in[4];
    const float* pcv  = (const float*)d_in[5 + o];
    const float* pcov = (const float*)d_in[6 + o];
    const float* emb  = (const float*)d_in[7 + o];
    const float* Wxc  = (const float*)d_in[8 + o];
    const float* bxc  = (const float*)d_in[9 + o];
    const float* Wih  = (const float*)d_in[10 + o];
    const float* Whh  = (const float*)d_in[11 + o];
    const float* bih  = (const float*)d_in[12 + o];
    const float* bhh  = (const float*)d_in[13 + o];
    const float* Wh   = (const float*)d_in[14 + o];
    const float* bh   = (const float*)d_in[15 + o];
    const float* Ws   = (const float*)d_in[16 + o];
    const float* bs   = (const float*)d_in[17 + o];
    const float* Wc   = (const float*)d_in[18 + o];
    const float* bc   = (const float*)d_in[19 + o];
    const float* vv   = (const float*)d_in[20 + o];
    const float* Wv1  = (const float*)d_in[21 + o];
    const float* bv1  = (const float*)d_in[22 + o];
    const float* Wv2  = (const float*)d_in[23 + o];
    const float* bv2  = (const float*)d_in[24 + o];
    const float* Wpg  = (const float*)d_in[25 + o];
    const float* bpg  = (const float*)d_in[26 + o];

    float* sc;
    cudaGetSymbolAddress((void**)&sc, g_scratch);
    __half* hh;
    cudaGetSymbolAddress((void**)&hh, g_half);
    cudaFuncSetAttribute(gemma, cudaFuncAttributeMaxDynamicSharedMemorySize, 2 * GA_BUF);
    cudaFuncSetAttribute(gemml, cudaFuncAttributeMaxDynamicSharedMemorySize, 2 * GA_BUF);

    float* out   = (float*)d_out;
    float* o_fd  = out;                       // 128*50050
    float* o_h   = out + 6406400;             // 128*512
    float* o_c   = o_h + 65536;               // 128*512
    float* o_ctx = o_c + 65536;               // 128*1024
    float* o_at  = o_ctx + 131072;            // 128*400
    float* o_pg  = o_at + 51200;              // 128
    float* o_cov = o_pg + 128;                // 128*400

    float* xbuf = sc + OFF_X;
    float* gbuf = sc + OFF_GATES;
    float* wsh  = sc + OFF_WSH;
    float* ebuf = sc + OFF_E;
    float* vsum = sc + OFF_VSUM;
    __half* whh  = hh + HOFF_WH;
    __half* hidh = hh + HOFF_HID;

    // 1. fused prep: Wh->fp16 + epc build + bias inits + zeros
    k_prep<<<(PREP_TOTAL + 255) / 256, 256>>>(Wh, whh, pt, emb, pcv, bxc, bs, bv1,
                                              sc + OFF_EPC, xbuf, gbuf, wsh, sc + OFF_HID,
                                              ebuf, vsum, o_fd);
    // 2. x = [emb|pcv] @ Wxc.T + bxc   (split-K 12)
    gemm2<<<dim3(1, 1, 12), 256>>>(sc + OFF_EPC, Wxc, xbuf, 128, 128, 1152, 96);
    // 3. gates = x @ W_ih.T + h0 @ W_hh.T  (split-K 4 each)
    gemm2<<<dim3(16, 1, 4), 256>>>(xbuf, Wih, gbuf, 128, 2048, 128, 32);
    gemm2<<<dim3(16, 1, 4), 256>>>(h0, Whh, gbuf, 128, 2048, 512, 128);
    // 4. LSTM pointwise
    k_lstm<<<(B_ * H_ + 255) / 256, 256>>>(gbuf, c0, bih, bhh, o_h, o_c,
                                           sc + OFF_SH, sc + OFF_HC);
    // 5. sWs = s_hat @ Ws.T + bs  (split-K 8)
    gemm2<<<dim3(8, 1, 8), 256>>>(sc + OFF_SH, Ws, wsh, 128, 1024, 1024, 128);
    // 6. attention logits e (fp32 enc inline-converted, fused epilogue)
    gemma<<<dim3(4, 400), 512, 2 * GA_BUF>>>(enc, whh, bh, bc, wsh, Wc, vv, pcov, ebuf);
    // 7. attn softmax + coverage
    k_attn_softmax<<<128, 128>>>(ebuf, pcov, o_at, o_cov);
    // 8. context (fp32 enc)
    k_context<<<dim3(8, 128), 128>>>(o_at, enc, o_ctx, sc + OFF_HC);
    // 9. hidden = [h|context] @ Wv1.T + bv1  (split-K 8)
    gemm2<<<dim3(4, 1, 8), 256>>>(sc + OFF_HC, Wv1, sc + OFF_HID, 128, 512, 1536, 192);
    // 10. hid -> fp16; exp-logits -> fd + row sums (fp32 Wv2 inline-converted)
    k_h2<<<(32768 + 255) / 256, 256>>>(sc + OFF_HID, hidh);
    gemml<<<dim3(196, 1), 512, 2 * GA_BUF>>>(hidh, Wv2, bv2, o_fd, vsum, V_);
    // 11. p_gen
    k_pgen<<<128, 256>>>(sc + OFF_SH, o_ctx, xbuf, Wpg, bpg, o_pg);
    // 12. scale + pointer scatter
    k_scale<<<(B_ * V_ + 255) / 256, 256>>>(o_fd, o_pg, vsum);
    k_scatter<<<(B_ * S_ + 255) / 256, 256>>>(o_at, o_pg, eie, o_fd);
}